// round 13
// baseline (speedup 1.0000x reference)
#include <cuda_runtime.h>
#include <cuda_bf16.h>
#include <cstdint>
#include <cfloat>

// ------------------------------------------------------------------
// device scratch (static — no allocs allowed)
// ------------------------------------------------------------------
__device__ __nv_bfloat16 g_zhi[65536ull * 512];   // bf16(z) transposed [n][c]
__device__ float         g_zt [65536ull * 512];   // fp32 z transposed [n][c]
__device__ __nv_bfloat16 g_cbhi[2048ull * 512];   // bf16(codebook) [e][c]
__device__ float    g_cbT[512ull * 2048];         // fp32 codebook transposed [c][e]
__device__ float    g_e2[2048];                   // fp32 ||e||^2 (warp-tree, same as R1)
__device__ int      g_idx[65536];
__device__ uint32_t g_cand[65536][48];            // packed keys: (q(d)<<11)|idx
__device__ float    g_d1[65536];                  // d_kernel of selected code (exact after rescore/fixup)
__device__ float    g_z2p[16ull * 65536];         // per-(cblock,pixel) ||z||^2 partials
__device__ int      g_resc[65536];
__device__ int      g_nresc;
__device__ int      g_fix[65536];
__device__ int      g_nfix;
__device__ double   g_partial[1024];

static constexpr float W_AMB  = 0.52f;  // ~7 sigma bf16 noise + key quantization margin
static constexpr float INV256 = 1.0f / 256.0f;

// ------------------------------------------------------------------
// PTX helpers (baseline PTX only — no tcgen05 on this toolchain target)
// ------------------------------------------------------------------
__device__ __forceinline__ uint32_t smem_u32(const void* p) {
    uint32_t a;
    asm("{ .reg .u64 t; cvta.to.shared.u64 t, %1; cvt.u32.u64 %0, t; }" : "=r"(a) : "l"(p));
    return a;
}
__device__ __forceinline__ void cp16(uint32_t dst, const void* src) {
    uint64_t g = __cvta_generic_to_global(src);
    asm volatile("cp.async.cg.shared.global [%0], [%1], 16;" :: "r"(dst), "l"(g) : "memory");
}
#define CP_COMMIT() asm volatile("cp.async.commit_group;" ::: "memory")
#define CP_WAIT(N)  asm volatile("cp.async.wait_group %0;" :: "n"(N) : "memory")

__device__ __forceinline__ uint32_t swz(uint32_t x) { return x ^ ((x >> 3) & 0x70); }

__device__ __forceinline__ void ldsm4(uint32_t& r0, uint32_t& r1, uint32_t& r2, uint32_t& r3,
                                      uint32_t addr) {
    asm volatile("ldmatrix.sync.aligned.m8n8.x4.shared.b16 {%0,%1,%2,%3}, [%4];"
                 : "=r"(r0), "=r"(r1), "=r"(r2), "=r"(r3) : "r"(addr));
}
__device__ __forceinline__ void mma16816(float& c0, float& c1, float& c2, float& c3,
                                         uint32_t a0, uint32_t a1, uint32_t a2, uint32_t a3,
                                         uint32_t b0, uint32_t b1) {
    asm volatile("mma.sync.aligned.m16n8k16.row.col.f32.bf16.bf16.f32 "
                 "{%0,%1,%2,%3}, {%4,%5,%6,%7}, {%8,%9}, {%0,%1,%2,%3};"
                 : "+f"(c0), "+f"(c1), "+f"(c2), "+f"(c3)
                 : "r"(a0), "r"(a1), "r"(a2), "r"(a3), "r"(b0), "r"(b1));
}

// packed key helpers: key = (round(max(d,0)*256) << 11) | idx ; smaller = better,
// exact-tie resolves to lower idx automatically.
__device__ __forceinline__ uint32_t pack_key(float d, int idx) {
    return (__float2uint_rn(fmaxf(d, 0.0f) * 256.0f) << 11) | (uint32_t)idx;
}
__device__ __forceinline__ float key_d(uint32_t k) { return (float)(k >> 11) * INV256; }

// branchless top-3 insert on packed keys (6 umin/umax)
#define INS_PK(S, K) do {                                                      \
    uint32_t _h0 = max(tk[S][0], (K)); tk[S][0] = min(tk[S][0], (K));          \
    uint32_t _h1 = max(tk[S][1], _h0); tk[S][1] = min(tk[S][1], _h0);          \
    tk[S][2] = min(tk[S][2], _h1);                                             \
} while (0)

// ------------------------------------------------------------------
// prep: blocks [0,256): codebook -> bf16 + fp32 ||e||^2 (R1 arithmetic);
//       blocks [256,1280): tiled transpose cb -> g_cbT [c][e]
// ------------------------------------------------------------------
__global__ __launch_bounds__(256) void prep_cb_kernel(const float* __restrict__ cb) {
    if (blockIdx.x == 0 && threadIdx.x == 0) { g_nfix = 0; g_nresc = 0; }

    if (blockIdx.x < 256) {
        int warp = (blockIdx.x * blockDim.x + threadIdx.x) >> 5;
        int lane = threadIdx.x & 31;
        const float* row = cb + (size_t)warp * 512;
        float s = 0.f;
        #pragma unroll 4
        for (int c = lane; c < 512; c += 32) {
            float v = row[c];
            s += v * v;
            g_cbhi[(size_t)warp * 512 + c] = __float2bfloat16(v);
        }
        #pragma unroll
        for (int o = 16; o; o >>= 1) s += __shfl_xor_sync(0xffffffffu, s, o);
        if (lane == 0) g_e2[warp] = s;
    } else {
        // transpose tile: 32 codes x 32 channels via smem
        __shared__ float ts[32][33];
        const int tb = blockIdx.x - 256;        // 0..1023
        const int e0 = (tb & 63) * 32;
        const int c0 = (tb >> 6) * 32;
        const int tx = threadIdx.x & 31;
        const int ty = threadIdx.x >> 5;        // 0..7
        #pragma unroll
        for (int i = 0; i < 4; i++) {
            int e = e0 + ty + i * 8;
            ts[ty + i * 8][tx] = cb[(size_t)e * 512 + c0 + tx];
        }
        __syncthreads();
        #pragma unroll
        for (int i = 0; i < 4; i++) {
            int c = c0 + ty + i * 8;
            g_cbT[(size_t)c * 2048 + e0 + tx] = ts[tx][ty + i * 8];
        }
    }
}

// ------------------------------------------------------------------
// prep: z [B,C,H,W] -> transposed bf16 + fp32 planes [n][c] + ||z||^2 partials
// ------------------------------------------------------------------
__global__ __launch_bounds__(256) void prep_z_kernel(const float* __restrict__ z) {
    __shared__ float s[32][33];
    const int tx = threadIdx.x, ty = threadIdx.y;
    const int n0 = blockIdx.x * 32;
    const int c0 = blockIdx.y * 32;
    const int b  = n0 >> 12;
    const int hw = n0 & 4095;
    #pragma unroll
    for (int i = 0; i < 4; i++) {
        int c = c0 + ty + i * 8;
        s[ty + i * 8][tx] = z[((size_t)b * 512 + c) * 4096 + hw + tx];
    }
    __syncthreads();
    #pragma unroll
    for (int i = 0; i < 4; i++) {
        float v = s[tx][ty + i * 8];      // pixel n0+ty+i*8, channel c0+tx
        size_t idx = (size_t)(n0 + ty + i * 8) * 512 + c0 + tx;
        g_zhi[idx] = __float2bfloat16(v);
        g_zt[idx]  = v;
        float sq = v * v;                 // reduce over tx = 32 channels
        #pragma unroll
        for (int o = 16; o; o >>= 1) sq += __shfl_xor_sync(0xffffffffu, sq, o);
        if (tx == 0) g_z2p[(size_t)blockIdx.y * 65536 + n0 + ty + i * 8] = sq;
    }
}

// ------------------------------------------------------------------
// main: HMMA distance GEMM + windowed packed-top-3 candidate tracking
// CTA: 64 pixels x 2048 codes, 256 threads (8 warps), 2 CTAs/SM.
// Warps as 2(M) x 4(N); warp tile 32x32. A resident (64KB), B 2-stage (32KB).
// ks loop software-pipelined with double-buffered LDSM fragments.
// ------------------------------------------------------------------
__global__ __launch_bounds__(256, 2) void vq_mma_kernel() {
    extern __shared__ char sm[];
    const uint32_t sA = smem_u32(sm);           // 64KB: 8 kt-tiles of [64m][128B]
    const uint32_t sB = sA + 65536u;            // 2 stages x 16KB
    uint32_t* candk = (uint32_t*)sm;            // merge reuse: [64][48]

    const int t = threadIdx.x;
    const int lane = t & 31;
    const int w = t >> 5;
    const int wm = w >> 2;      // 0..1  (M, 32 rows each)
    const int wn = w & 3;       // 0..3  (N, 32 cols each)
    const int n0 = blockIdx.x * 64;

    // ---- A resident load (once): 4096 16B-units over 256 threads ----
    #pragma unroll
    for (int i = 0; i < 16; i++) {
        int U = t + 256 * i;
        int m = U >> 6, r = U & 63;             // r = kt*8 + j
        int kt = r >> 3, j = r & 7;
        cp16(sA + (uint32_t)kt * 8192u + swz((uint32_t)m * 128u + (uint32_t)j * 16u),
             g_zhi + ((size_t)(n0 + m)) * 512 + r * 8);
    }
    CP_COMMIT();

    auto loadB = [&](int c) {
        int nt = c >> 3, kt = c & 7, s = c & 1;
        #pragma unroll
        for (int i = 0; i < 4; i++) {
            int U = t + 256 * i;
            int n = U >> 3, j = U & 7;
            cp16(sB + (uint32_t)s * 16384u + swz((uint32_t)n * 128u + (uint32_t)j * 16u),
                 g_cbhi + ((size_t)(nt * 128 + n)) * 512 + kt * 64 + j * 8);
        }
    };
    loadB(0);
    CP_COMMIT();

    // fragment double buffers + packed top-3 per row-slot
    uint32_t aF[2][2][4], bF[2][2][4];
    float acc[2][4][4];
    uint32_t tk[4][3];
    #pragma unroll
    for (int s = 0; s < 4; s++)
        #pragma unroll
        for (int k = 0; k < 3; k++) tk[s][k] = 0xFFFFFFFFu;

    const int am  = ((lane >> 3) & 1) * 8 + (lane & 7);
    const int akO = (lane >> 4) * 16;
    const int bn  = (lane >> 4) * 8 + (lane & 7);
    const int bkO = ((lane >> 3) & 1) * 16;

    for (int c = 0; c < 128; c++) {
        const int nt = c >> 3, kt = c & 7, s = c & 1;

        CP_WAIT(0);
        __syncthreads();
        if (c + 1 < 128) { loadB(c + 1); CP_COMMIT(); }

        if (kt == 0) {
            #pragma unroll
            for (int f = 0; f < 2; f++)
                #pragma unroll
                for (int g = 0; g < 4; g++)
                    #pragma unroll
                    for (int q = 0; q < 4; q++) acc[f][g][q] = 0.f;
        }

        const uint32_t aT = sA + (uint32_t)kt * 8192u;
        const uint32_t bT = sB + (uint32_t)s * 16384u;

        auto ldA = [&](int buf, int ks) {
            #pragma unroll
            for (int f = 0; f < 2; f++) {
                uint32_t off = (uint32_t)((wm * 32 + f * 16 + am) * 128 + ks * 32 + akO);
                ldsm4(aF[buf][f][0], aF[buf][f][1], aF[buf][f][2], aF[buf][f][3],
                      aT + swz(off));
            }
        };
        auto ldB = [&](int buf, int ks) {
            #pragma unroll
            for (int g2 = 0; g2 < 2; g2++) {
                uint32_t off = (uint32_t)((wn * 32 + g2 * 16 + bn) * 128 + ks * 32 + bkO);
                ldsm4(bF[buf][g2][0], bF[buf][g2][1], bF[buf][g2][2], bF[buf][g2][3],
                      bT + swz(off));
            }
        };

        // software-pipelined ks loop: prefetch ks+1 fragments before MMAs of ks
        ldA(0, 0); ldB(0, 0);
        #pragma unroll
        for (int ks = 0; ks < 4; ks++) {
            const int cur = ks & 1, nxt = cur ^ 1;
            if (ks < 3) { ldA(nxt, ks + 1); ldB(nxt, ks + 1); }
            #pragma unroll
            for (int f = 0; f < 2; f++)
                #pragma unroll
                for (int g = 0; g < 4; g++)
                    mma16816(acc[f][g][0], acc[f][g][1], acc[f][g][2], acc[f][g][3],
                             aF[cur][f][0], aF[cur][f][1], aF[cur][f][2], aF[cur][f][3],
                             bF[cur][g >> 1][(g & 1) * 2], bF[cur][g >> 1][(g & 1) * 2 + 1]);
        }

        if (kt == 7) {
            #pragma unroll
            for (int f = 0; f < 2; f++) {
                #pragma unroll
                for (int g = 0; g < 4; g++) {
                    int nfirst = nt * 128 + wn * 32 + g * 8 + (lane & 3) * 2;
                    float e2a = g_e2[nfirst], e2b = g_e2[nfirst + 1];
                    uint32_t k0 = pack_key(e2a - 2.0f * acc[f][g][0], nfirst);
                    uint32_t k1 = pack_key(e2b - 2.0f * acc[f][g][1], nfirst + 1);
                    uint32_t k2 = pack_key(e2a - 2.0f * acc[f][g][2], nfirst);
                    uint32_t k3 = pack_key(e2b - 2.0f * acc[f][g][3], nfirst + 1);
                    INS_PK(2 * f,     k0);
                    INS_PK(2 * f,     k1);
                    INS_PK(2 * f + 1, k2);
                    INS_PK(2 * f + 1, k3);
                }
            }
        }
    }
    __syncthreads();   // all warps done reading sA/sB before candk aliases them

    // ---- merge: 16 thread-slots x top-3 = 48 packed candidates per pixel row ----
    const int tslot = wn * 4 + (lane & 3);      // 0..15
    #pragma unroll
    for (int f = 0; f < 2; f++) {
        #pragma unroll
        for (int h = 0; h < 2; h++) {
            int row = wm * 32 + f * 16 + h * 8 + (lane >> 2);
            #pragma unroll
            for (int k = 0; k < 3; k++)
                candk[row * 48 + tslot * 3 + k] = tk[2 * f + h][k];
        }
    }
    __syncthreads();

    if (t < 64) {
        const int row = t;
        const int n = n0 + row;
        uint32_t k1 = 0xFFFFFFFFu, k2 = 0xFFFFFFFFu;
        #pragma unroll 4
        for (int j = 0; j < 48; j++) {
            uint32_t k = candk[row * 48 + j];
            uint32_t hi = max(k, k1);
            k1 = min(k, k1);
            k2 = min(hi, k2);
        }
        const float d1 = key_d(k1), d2 = key_d(k2);
        // soundness: a true in-window candidate can only be dropped from a slot
        // if that slot holds >=3 smaller (hence in-window) keys -> detect via
        // slot's 3rd-best being in-window
        bool flag = false;
        #pragma unroll
        for (int q = 0; q < 16; q++)
            flag |= (key_d(candk[row * 48 + q * 3 + 2]) < d1 + W_AMB);
        g_idx[n] = (int)(k1 & 0x7FFu);
        g_d1[n] = d1;
        #pragma unroll 4
        for (int j = 0; j < 48; j++) g_cand[n][j] = candk[row * 48 + j];
        if (flag) {
            int p = atomicAdd(&g_nfix, 1);
            g_fix[p] = n;
        } else if (d2 - d1 < W_AMB) {
            int p = atomicAdd(&g_nresc, 1);
            g_resc[p] = n;
        }
    }
}

// ------------------------------------------------------------------
// fixup: full re-argmin over 2048 codes via TRANSPOSED codebook
// (coalesced), per-code dot is SEQUENTIAL c-order fmaf (R1 numerics).
// Thread tid owns codes {4tid..4tid+3} and {4tid+1024..+3}.
// ------------------------------------------------------------------
__global__ __launch_bounds__(256) void fixup_kernel() {
    __shared__ float zr[512];
    __shared__ float rd[256];
    __shared__ int   ri[256];
    const int tid = threadIdx.x;
    const int nf = g_nfix;

    for (int f = blockIdx.x; f < nf; f += gridDim.x) {
        const int n = g_fix[f];
        for (int c = tid; c < 128; c += 256)
            *(float4*)&zr[c * 4] = *(const float4*)&g_zt[(size_t)n * 512 + c * 4];
        __syncthreads();

        const int e0 = tid * 4;
        float dot[8];
        #pragma unroll
        for (int j = 0; j < 8; j++) dot[j] = 0.f;
        #pragma unroll 4
        for (int c = 0; c < 512; c++) {
            float zv = zr[c];
            float4 v0 = *(const float4*)&g_cbT[(size_t)c * 2048 + e0];
            float4 v1 = *(const float4*)&g_cbT[(size_t)c * 2048 + e0 + 1024];
            dot[0] = fmaf(zv, v0.x, dot[0]);
            dot[1] = fmaf(zv, v0.y, dot[1]);
            dot[2] = fmaf(zv, v0.z, dot[2]);
            dot[3] = fmaf(zv, v0.w, dot[3]);
            dot[4] = fmaf(zv, v1.x, dot[4]);
            dot[5] = fmaf(zv, v1.y, dot[5]);
            dot[6] = fmaf(zv, v1.z, dot[6]);
            dot[7] = fmaf(zv, v1.w, dot[7]);
        }
        float best = FLT_MAX; int bidx = 0x7fffffff;
        #pragma unroll
        for (int j = 0; j < 8; j++) {
            int e = (j < 4) ? (e0 + j) : (e0 + 1024 + (j - 4));   // ascending in-thread
            float d = g_e2[e] - 2.0f * dot[j];
            if (d < best || (d == best && e < bidx)) { best = d; bidx = e; }
        }
        rd[tid] = best; ri[tid] = bidx;
        __syncthreads();
        #pragma unroll
        for (int sft = 128; sft; sft >>= 1) {
            if (tid < sft) {
                float d2 = rd[tid + sft]; int i2 = ri[tid + sft];
                if (d2 < rd[tid] || (d2 == rd[tid] && i2 < ri[tid])) {
                    rd[tid] = d2; ri[tid] = i2;
                }
            }
            __syncthreads();
        }
        if (tid == 0) { g_idx[n] = ri[0]; g_d1[n] = rd[0]; }
        __syncthreads();
    }
}

// ------------------------------------------------------------------
// rescore: exact fp32 over ONLY the in-window candidates, SEQUENTIAL
// k-order FMA (bitwise-identical arithmetic to the R1 baseline).
// Writes exact d to g_d1.
// ------------------------------------------------------------------
__global__ __launch_bounds__(256) void rescore_kernel(const float* __restrict__ cb) {
    __shared__ float zr[8][512];
    const int lane = threadIdx.x & 31;
    const int w = threadIdx.x >> 5;
    const int total = g_nresc;
    for (int p = blockIdx.x * 8 + w; p < total; p += gridDim.x * 8) {
        const int n = g_resc[p];
        const float thr = g_d1[n] + W_AMB;
        for (int i = lane; i < 128; i += 32)
            *(float4*)&zr[w][i * 4] = *(const float4*)&g_zt[(size_t)n * 512 + i * 4];
        __syncwarp();
        float best = FLT_MAX; int bid = 0x7fffffff;
        #pragma unroll
        for (int j0 = 0; j0 < 2; j0++) {
            int j = j0 * 32 + lane;
            float d = FLT_MAX; int id = 0x7fffffff;
            uint32_t key = (j < 48) ? g_cand[n][j] : 0xFFFFFFFFu;
            if (j < 48 && key_d(key) < thr) {
                id = (int)(key & 0x7FFu);
                const float4* cr4 = (const float4*)(cb + (size_t)id * 512);
                float dot = 0.f;
                #pragma unroll 4
                for (int c4 = 0; c4 < 128; c4++) {
                    float4 v = cr4[c4];
                    dot = fmaf(zr[w][c4 * 4 + 0], v.x, dot);
                    dot = fmaf(zr[w][c4 * 4 + 1], v.y, dot);
                    dot = fmaf(zr[w][c4 * 4 + 2], v.z, dot);
                    dot = fmaf(zr[w][c4 * 4 + 3], v.w, dot);
                }
                d = g_e2[id] - 2.0f * dot;
            }
            if (d < best || (d == best && id < bid)) { best = d; bid = id; }
        }
        #pragma unroll
        for (int o = 16; o; o >>= 1) {
            float od = __shfl_xor_sync(0xffffffffu, best, o);
            int   oi = __shfl_xor_sync(0xffffffffu, bid, o);
            if (od < best || (od == best && oi < bid)) { best = od; bid = oi; }
        }
        if (lane == 0) { g_idx[n] = bid; g_d1[n] = best; }
        __syncwarp();
    }
}

// ------------------------------------------------------------------
// gather: chunked smem staging (64 channels/chunk) + coalesced
// transposed WRITE ONLY (loss comes from d values, no z read).
// ------------------------------------------------------------------
__global__ __launch_bounds__(256) void gather_kernel(
    const float* __restrict__ cb, float* __restrict__ out) {

    __shared__ float  smf[64 * 65];
    __shared__ int    idxs[64];

    const int t  = threadIdx.x;
    const int n0 = blockIdx.x * 64;
    if (t < 64) idxs[t] = g_idx[n0 + t];
    __syncthreads();

    const int b  = n0 >> 12;
    const int hw = n0 & 4095;
    const size_t base = (size_t)b * 512 * 4096 + hw;

    const int m  = t & 63;
    const int c0 = t >> 6;          // 0..3
    const int sr = t >> 4;          // staging row group 0..15
    const int sc = (t & 15) * 4;    // staging channel 0..60

    #pragma unroll 1
    for (int cc = 0; cc < 8; cc++) {
        #pragma unroll
        for (int it = 0; it < 4; it++) {
            int r = it * 16 + sr;
            float4 v = *(const float4*)(cb + (size_t)idxs[r] * 512 + cc * 64 + sc);
            smf[(sc + 0) * 65 + r] = v.x;
            smf[(sc + 1) * 65 + r] = v.y;
            smf[(sc + 2) * 65 + r] = v.z;
            smf[(sc + 3) * 65 + r] = v.w;
        }
        __syncthreads();
        #pragma unroll 4
        for (int i = 0; i < 16; i++) {
            int cl = c0 + i * 4;
            out[base + (size_t)(cc * 64 + cl) * 4096 + m] = smf[cl * 65 + m];
        }
        __syncthreads();
    }
}

// ------------------------------------------------------------------
// loss partials: blocks 0..63 sum g_z2p (16384 each), 64..67 sum g_d1.
// Fixed per-thread partitions + fp64 -> deterministic.
// ------------------------------------------------------------------
__global__ __launch_bounds__(256) void loss_part_kernel() {
    __shared__ double sd[256];
    const int t = threadIdx.x, b = blockIdx.x;
    const float* src = (b < 64) ? (g_z2p + (size_t)b * 16384)
                                : (g_d1 + (size_t)(b - 64) * 16384);
    double a0 = 0, a1 = 0, a2 = 0, a3 = 0;
    for (int i = t * 4; i < 16384; i += 1024) {
        float4 v = *(const float4*)(src + i);
        a0 += v.x; a1 += v.y; a2 += v.z; a3 += v.w;
    }
    sd[t] = (a0 + a1) + (a2 + a3);
    __syncthreads();
    #pragma unroll
    for (int s = 128; s; s >>= 1) {
        if (t < s) sd[t] += sd[t + s];
        __syncthreads();
    }
    if (t == 0) g_partial[b] = sd[0];
}

// ------------------------------------------------------------------
// finalize: loss = 1.25 * (sum_d + sum_z2) / zq_elems
// ------------------------------------------------------------------
__global__ void finalize_kernel(float* __restrict__ out, int out_size, int zq_elems) {
    if (threadIdx.x == 0) {
        double s = 0.0;
        for (int i = 0; i < 68; i++) s += g_partial[i];
        if (out_size > zq_elems)
            out[zq_elems] = (float)(1.25 * s / (double)zq_elems);
    }
}

// ------------------------------------------------------------------
// launch
// ------------------------------------------------------------------
extern "C" void kernel_launch(void* const* d_in, const int* in_sizes, int n_in,
                              void* d_out, int out_size) {
    const float* z  = (const float*)d_in[0];   // [16,512,64,64]
    const float* cb = (const float*)d_in[1];   // [2048,512]
    float* out = (float*)d_out;
    const int zq_elems = in_sizes[0];          // 33554432

    const int SMEM_MAIN = 65536 + 2 * 16384;   // A resident (64KB) + 2 B stages (32KB)
    cudaFuncSetAttribute(vq_mma_kernel,
                         cudaFuncAttributeMaxDynamicSharedMemorySize, SMEM_MAIN);

    prep_cb_kernel<<<1280, 256>>>(cb);                  // launch 0 (e2/bf16 + cbT transpose)
    prep_z_kernel<<<dim3(2048, 16), dim3(32, 8)>>>(z);  // launch 1
    vq_mma_kernel<<<1024, 256, SMEM_MAIN>>>();          // launch 2
    fixup_kernel<<<256, 256>>>();                       // launch 3 -> profiled
    rescore_kernel<<<512, 256>>>(cb);                   // launch 4
    gather_kernel<<<1024, 256>>>(cb, out);              // launch 5
    loss_part_kernel<<<68, 256>>>();                    // launch 6
    finalize_kernel<<<1, 32>>>(out, out_size, zq_elems);// launch 7
}

// round 14
// speedup vs baseline: 1.1591x; 1.1591x over previous
#include <cuda_runtime.h>
#include <cuda_bf16.h>
#include <cstdint>
#include <cfloat>

// ------------------------------------------------------------------
// device scratch (static — no allocs allowed)
// ------------------------------------------------------------------
__device__ __nv_bfloat16 g_zhi[65536ull * 512];   // bf16(z) transposed [n][c]
__device__ float         g_zt [65536ull * 512];   // fp32 z transposed [n][c]
__device__ __nv_bfloat16 g_cbhi[2048ull * 512];   // bf16(codebook) [e][c]
__device__ float    g_cbS[16ull * 512 * 128];     // fp32 codebook slot-major [q][c][i]
__device__ float    g_e2[2048];                   // fp32 ||e||^2 (warp-tree, same as R1)
__device__ int      g_idx[65536];
__device__ uint32_t g_cand[65536][48];            // packed keys: (q(d)<<11)|idx
__device__ float    g_d1[65536];                  // d_kernel of selected code (exact after rescore/fixup)
__device__ float    g_z2p[16ull * 65536];         // per-(cblock,pixel) ||z||^2 partials
__device__ int      g_resc[65536];
__device__ int      g_nresc;
__device__ int      g_fix[65536];                 // packed (n<<16)|slot_mask
__device__ int      g_nfix;
__device__ double   g_partial[1024];

static constexpr float W_AMB  = 0.52f;  // ~7 sigma bf16 noise + key quantization margin
static constexpr float INV256 = 1.0f / 256.0f;

// ------------------------------------------------------------------
// PTX helpers (baseline PTX only — no tcgen05 on this toolchain target)
// ------------------------------------------------------------------
__device__ __forceinline__ uint32_t smem_u32(const void* p) {
    uint32_t a;
    asm("{ .reg .u64 t; cvta.to.shared.u64 t, %1; cvt.u32.u64 %0, t; }" : "=r"(a) : "l"(p));
    return a;
}
__device__ __forceinline__ void cp16(uint32_t dst, const void* src) {
    uint64_t g = __cvta_generic_to_global(src);
    asm volatile("cp.async.cg.shared.global [%0], [%1], 16;" :: "r"(dst), "l"(g) : "memory");
}
#define CP_COMMIT() asm volatile("cp.async.commit_group;" ::: "memory")
#define CP_WAIT(N)  asm volatile("cp.async.wait_group %0;" :: "n"(N) : "memory")

__device__ __forceinline__ uint32_t swz(uint32_t x) { return x ^ ((x >> 3) & 0x70); }

__device__ __forceinline__ void ldsm4(uint32_t& r0, uint32_t& r1, uint32_t& r2, uint32_t& r3,
                                      uint32_t addr) {
    asm volatile("ldmatrix.sync.aligned.m8n8.x4.shared.b16 {%0,%1,%2,%3}, [%4];"
                 : "=r"(r0), "=r"(r1), "=r"(r2), "=r"(r3) : "r"(addr));
}
__device__ __forceinline__ void mma16816(float& c0, float& c1, float& c2, float& c3,
                                         uint32_t a0, uint32_t a1, uint32_t a2, uint32_t a3,
                                         uint32_t b0, uint32_t b1) {
    asm volatile("mma.sync.aligned.m16n8k16.row.col.f32.bf16.bf16.f32 "
                 "{%0,%1,%2,%3}, {%4,%5,%6,%7}, {%8,%9}, {%0,%1,%2,%3};"
                 : "+f"(c0), "+f"(c1), "+f"(c2), "+f"(c3)
                 : "r"(a0), "r"(a1), "r"(a2), "r"(a3), "r"(b0), "r"(b1));
}

// packed key helpers: key = (round(max(d,0)*256) << 11) | idx ; smaller = better,
// exact-tie resolves to lower idx automatically.
__device__ __forceinline__ uint32_t pack_key(float d, int idx) {
    return (__float2uint_rn(fmaxf(d, 0.0f) * 256.0f) << 11) | (uint32_t)idx;
}
__device__ __forceinline__ float key_d(uint32_t k) { return (float)(k >> 11) * INV256; }

// slot q, in-slot index i (ascending i <-> ascending code id)
__device__ __forceinline__ int slot_code(int q, int i) {
    return ((i >> 3) << 7) + ((q >> 2) << 5) + (((i >> 1) & 3) << 3) + ((q & 3) << 1) + (i & 1);
}

// branchless top-3 insert on packed keys (6 umin/umax)
#define INS_PK(S, K) do {                                                      \
    uint32_t _h0 = max(tk[S][0], (K)); tk[S][0] = min(tk[S][0], (K));          \
    uint32_t _h1 = max(tk[S][1], _h0); tk[S][1] = min(tk[S][1], _h0);          \
    tk[S][2] = min(tk[S][2], _h1);                                             \
} while (0)

// ------------------------------------------------------------------
// prep: blocks [0,256): codebook -> bf16 + fp32 ||e||^2 (R1 arithmetic);
//       blocks [256,1280): build slot-major codebook g_cbS
// ------------------------------------------------------------------
__global__ __launch_bounds__(256) void prep_cb_kernel(const float* __restrict__ cb) {
    if (blockIdx.x == 0 && threadIdx.x == 0) { g_nfix = 0; g_nresc = 0; }

    if (blockIdx.x < 256) {
        int warp = (blockIdx.x * blockDim.x + threadIdx.x) >> 5;
        int lane = threadIdx.x & 31;
        const float* row = cb + (size_t)warp * 512;
        float s = 0.f;
        #pragma unroll 4
        for (int c = lane; c < 512; c += 32) {
            float v = row[c];
            s += v * v;
            g_cbhi[(size_t)warp * 512 + c] = __float2bfloat16(v);
        }
        #pragma unroll
        for (int o = 16; o; o >>= 1) s += __shfl_xor_sync(0xffffffffu, s, o);
        if (lane == 0) g_e2[warp] = s;
    } else {
        // cbS: flat = ((q*512)+c)*128 + i ; coalesced writes, scattered reads
        const int tb = blockIdx.x - 256;            // 0..1023
        int flat0 = tb * 1024 + threadIdx.x;
        #pragma unroll
        for (int it = 0; it < 4; it++) {
            int flat = flat0 + it * 256;
            int i = flat & 127;
            int c = (flat >> 7) & 511;
            int q = flat >> 16;
            int e = slot_code(q, i);
            g_cbS[flat] = cb[(size_t)e * 512 + c];
        }
    }
}

// ------------------------------------------------------------------
// prep: z [B,C,H,W] -> transposed bf16 + fp32 planes [n][c] + ||z||^2 partials
// ------------------------------------------------------------------
__global__ __launch_bounds__(256) void prep_z_kernel(const float* __restrict__ z) {
    __shared__ float s[32][33];
    const int tx = threadIdx.x, ty = threadIdx.y;
    const int n0 = blockIdx.x * 32;
    const int c0 = blockIdx.y * 32;
    const int b  = n0 >> 12;
    const int hw = n0 & 4095;
    #pragma unroll
    for (int i = 0; i < 4; i++) {
        int c = c0 + ty + i * 8;
        s[ty + i * 8][tx] = z[((size_t)b * 512 + c) * 4096 + hw + tx];
    }
    __syncthreads();
    #pragma unroll
    for (int i = 0; i < 4; i++) {
        float v = s[tx][ty + i * 8];      // pixel n0+ty+i*8, channel c0+tx
        size_t idx = (size_t)(n0 + ty + i * 8) * 512 + c0 + tx;
        g_zhi[idx] = __float2bfloat16(v);
        g_zt[idx]  = v;
        float sq = v * v;                 // reduce over tx = 32 channels
        #pragma unroll
        for (int o = 16; o; o >>= 1) sq += __shfl_xor_sync(0xffffffffu, sq, o);
        if (tx == 0) g_z2p[(size_t)blockIdx.y * 65536 + n0 + ty + i * 8] = sq;
    }
}

// ------------------------------------------------------------------
// main: HMMA distance GEMM + windowed packed-top-3 candidate tracking
// CTA: 64 pixels x 2048 codes, 256 threads (8 warps), 2 CTAs/SM.
// Warps as 2(M) x 4(N); warp tile 32x32. A resident (64KB), B 2-stage (32KB).
// ks loop software-pipelined with double-buffered LDSM fragments.
// ------------------------------------------------------------------
__global__ __launch_bounds__(256, 2) void vq_mma_kernel() {
    extern __shared__ char sm[];
    const uint32_t sA = smem_u32(sm);           // 64KB: 8 kt-tiles of [64m][128B]
    const uint32_t sB = sA + 65536u;            // 2 stages x 16KB
    uint32_t* candk = (uint32_t*)sm;            // merge reuse: [64][48]

    const int t = threadIdx.x;
    const int lane = t & 31;
    const int w = t >> 5;
    const int wm = w >> 2;      // 0..1  (M, 32 rows each)
    const int wn = w & 3;       // 0..3  (N, 32 cols each)
    const int n0 = blockIdx.x * 64;

    // ---- A resident load (once): 4096 16B-units over 256 threads ----
    #pragma unroll
    for (int i = 0; i < 16; i++) {
        int U = t + 256 * i;
        int m = U >> 6, r = U & 63;             // r = kt*8 + j
        int kt = r >> 3, j = r & 7;
        cp16(sA + (uint32_t)kt * 8192u + swz((uint32_t)m * 128u + (uint32_t)j * 16u),
             g_zhi + ((size_t)(n0 + m)) * 512 + r * 8);
    }
    CP_COMMIT();

    auto loadB = [&](int c) {
        int nt = c >> 3, kt = c & 7, s = c & 1;
        #pragma unroll
        for (int i = 0; i < 4; i++) {
            int U = t + 256 * i;
            int n = U >> 3, j = U & 7;
            cp16(sB + (uint32_t)s * 16384u + swz((uint32_t)n * 128u + (uint32_t)j * 16u),
                 g_cbhi + ((size_t)(nt * 128 + n)) * 512 + kt * 64 + j * 8);
        }
    };
    loadB(0);
    CP_COMMIT();

    // fragment double buffers + packed top-3 per row-slot
    uint32_t aF[2][2][4], bF[2][2][4];
    float acc[2][4][4];
    uint32_t tk[4][3];
    #pragma unroll
    for (int s = 0; s < 4; s++)
        #pragma unroll
        for (int k = 0; k < 3; k++) tk[s][k] = 0xFFFFFFFFu;

    const int am  = ((lane >> 3) & 1) * 8 + (lane & 7);
    const int akO = (lane >> 4) * 16;
    const int bn  = (lane >> 4) * 8 + (lane & 7);
    const int bkO = ((lane >> 3) & 1) * 16;

    for (int c = 0; c < 128; c++) {
        const int nt = c >> 3, kt = c & 7, s = c & 1;

        CP_WAIT(0);
        __syncthreads();
        if (c + 1 < 128) { loadB(c + 1); CP_COMMIT(); }

        if (kt == 0) {
            #pragma unroll
            for (int f = 0; f < 2; f++)
                #pragma unroll
                for (int g = 0; g < 4; g++)
                    #pragma unroll
                    for (int q = 0; q < 4; q++) acc[f][g][q] = 0.f;
        }

        const uint32_t aT = sA + (uint32_t)kt * 8192u;
        const uint32_t bT = sB + (uint32_t)s * 16384u;

        auto ldA = [&](int buf, int ks) {
            #pragma unroll
            for (int f = 0; f < 2; f++) {
                uint32_t off = (uint32_t)((wm * 32 + f * 16 + am) * 128 + ks * 32 + akO);
                ldsm4(aF[buf][f][0], aF[buf][f][1], aF[buf][f][2], aF[buf][f][3],
                      aT + swz(off));
            }
        };
        auto ldB = [&](int buf, int ks) {
            #pragma unroll
            for (int g2 = 0; g2 < 2; g2++) {
                uint32_t off = (uint32_t)((wn * 32 + g2 * 16 + bn) * 128 + ks * 32 + bkO);
                ldsm4(bF[buf][g2][0], bF[buf][g2][1], bF[buf][g2][2], bF[buf][g2][3],
                      bT + swz(off));
            }
        };

        // software-pipelined ks loop: prefetch ks+1 fragments before MMAs of ks
        ldA(0, 0); ldB(0, 0);
        #pragma unroll
        for (int ks = 0; ks < 4; ks++) {
            const int cur = ks & 1, nxt = cur ^ 1;
            if (ks < 3) { ldA(nxt, ks + 1); ldB(nxt, ks + 1); }
            #pragma unroll
            for (int f = 0; f < 2; f++)
                #pragma unroll
                for (int g = 0; g < 4; g++)
                    mma16816(acc[f][g][0], acc[f][g][1], acc[f][g][2], acc[f][g][3],
                             aF[cur][f][0], aF[cur][f][1], aF[cur][f][2], aF[cur][f][3],
                             bF[cur][g >> 1][(g & 1) * 2], bF[cur][g >> 1][(g & 1) * 2 + 1]);
        }

        if (kt == 7) {
            #pragma unroll
            for (int f = 0; f < 2; f++) {
                #pragma unroll
                for (int g = 0; g < 4; g++) {
                    int nfirst = nt * 128 + wn * 32 + g * 8 + (lane & 3) * 2;
                    float e2a = g_e2[nfirst], e2b = g_e2[nfirst + 1];
                    uint32_t k0 = pack_key(e2a - 2.0f * acc[f][g][0], nfirst);
                    uint32_t k1 = pack_key(e2b - 2.0f * acc[f][g][1], nfirst + 1);
                    uint32_t k2 = pack_key(e2a - 2.0f * acc[f][g][2], nfirst);
                    uint32_t k3 = pack_key(e2b - 2.0f * acc[f][g][3], nfirst + 1);
                    INS_PK(2 * f,     k0);
                    INS_PK(2 * f,     k1);
                    INS_PK(2 * f + 1, k2);
                    INS_PK(2 * f + 1, k3);
                }
            }
        }
    }
    __syncthreads();   // all warps done reading sA/sB before candk aliases them

    // ---- merge: 16 thread-slots x top-3 = 48 packed candidates per pixel row ----
    const int tslot = wn * 4 + (lane & 3);      // 0..15
    #pragma unroll
    for (int f = 0; f < 2; f++) {
        #pragma unroll
        for (int h = 0; h < 2; h++) {
            int row = wm * 32 + f * 16 + h * 8 + (lane >> 2);
            #pragma unroll
            for (int k = 0; k < 3; k++)
                candk[row * 48 + tslot * 3 + k] = tk[2 * f + h][k];
        }
    }
    __syncthreads();

    if (t < 64) {
        const int row = t;
        const int n = n0 + row;
        uint32_t k1 = 0xFFFFFFFFu, k2 = 0xFFFFFFFFu;
        #pragma unroll 4
        for (int j = 0; j < 48; j++) {
            uint32_t k = candk[row * 48 + j];
            uint32_t hi = max(k, k1);
            k1 = min(k, k1);
            k2 = min(hi, k2);
        }
        const float d1 = key_d(k1), d2 = key_d(k2);
        // per-slot overflow mask: slot q may have dropped in-window candidates
        // only if its 3rd-best is itself in-window
        uint32_t mask = 0;
        #pragma unroll
        for (int q = 0; q < 16; q++)
            if (key_d(candk[row * 48 + q * 3 + 2]) < d1 + W_AMB) mask |= (1u << q);
        g_idx[n] = (int)(k1 & 0x7FFu);
        g_d1[n] = d1;
        #pragma unroll 4
        for (int j = 0; j < 48; j++) g_cand[n][j] = candk[row * 48 + j];
        if (mask) {
            int p = atomicAdd(&g_nfix, 1);
            g_fix[p] = (int)(((uint32_t)n << 16) | mask);
        } else if (d2 - d1 < W_AMB) {
            int p = atomicAdd(&g_nresc, 1);
            g_resc[p] = n;
        }
    }
}

// ------------------------------------------------------------------
// fixup: warp per flagged pixel. Exact argmin over (all 48 candidates)
// U (full 128-code sets of flagged slots, via slot-major g_cbS with
// coalesced loads). Per-code dot = SEQUENTIAL c-order fmaf (R1 numerics).
// ------------------------------------------------------------------
__global__ __launch_bounds__(256) void fixup_kernel(const float* __restrict__ cb) {
    __shared__ float zr[8][512];
    const int lane = threadIdx.x & 31;
    const int w = threadIdx.x >> 5;
    const int total = g_nfix;
    for (int p = blockIdx.x * 8 + w; p < total; p += gridDim.x * 8) {
        const uint32_t rec = (uint32_t)g_fix[p];
        const int n = (int)(rec >> 16);
        uint32_t mask = rec & 0xFFFFu;
        for (int i = lane; i < 128; i += 32)
            *(float4*)&zr[w][i * 4] = *(const float4*)&g_zt[(size_t)n * 512 + i * 4];
        __syncwarp();

        float best = FLT_MAX; int bid = 0x7fffffff;

        // part A: all 48 candidates, exact
        #pragma unroll
        for (int j0 = 0; j0 < 2; j0++) {
            int j = j0 * 32 + lane;
            if (j < 48) {
                int id = (int)(g_cand[n][j] & 0x7FFu);
                const float4* cr4 = (const float4*)(cb + (size_t)id * 512);
                float dot = 0.f;
                #pragma unroll 4
                for (int c4 = 0; c4 < 128; c4++) {
                    float4 v = cr4[c4];
                    dot = fmaf(zr[w][c4 * 4 + 0], v.x, dot);
                    dot = fmaf(zr[w][c4 * 4 + 1], v.y, dot);
                    dot = fmaf(zr[w][c4 * 4 + 2], v.z, dot);
                    dot = fmaf(zr[w][c4 * 4 + 3], v.w, dot);
                }
                float d = g_e2[id] - 2.0f * dot;
                if (d < best || (d == best && id < bid)) { best = d; bid = id; }
            }
        }

        // part B: flagged slots, 4 codes/lane, coalesced slot-major loads
        while (mask) {
            int q = __ffs(mask) - 1; mask &= (mask - 1);
            const float* basep = g_cbS + ((size_t)q * 512) * 128 + lane * 4;
            float dot0 = 0.f, dot1 = 0.f, dot2 = 0.f, dot3 = 0.f;
            #pragma unroll 4
            for (int c = 0; c < 512; c++) {
                float zv = zr[w][c];
                float4 v = *(const float4*)(basep + (size_t)c * 128);
                dot0 = fmaf(zv, v.x, dot0);
                dot1 = fmaf(zv, v.y, dot1);
                dot2 = fmaf(zv, v.z, dot2);
                dot3 = fmaf(zv, v.w, dot3);
            }
            float dots[4] = { dot0, dot1, dot2, dot3 };
            #pragma unroll
            for (int j = 0; j < 4; j++) {
                int e = slot_code(q, lane * 4 + j);
                float d = g_e2[e] - 2.0f * dots[j];
                if (d < best || (d == best && e < bid)) { best = d; bid = e; }
            }
        }

        #pragma unroll
        for (int o = 16; o; o >>= 1) {
            float od = __shfl_xor_sync(0xffffffffu, best, o);
            int   oi = __shfl_xor_sync(0xffffffffu, bid, o);
            if (od < best || (od == best && oi < bid)) { best = od; bid = oi; }
        }
        if (lane == 0) { g_idx[n] = bid; g_d1[n] = best; }
        __syncwarp();
    }
}

// ------------------------------------------------------------------
// rescore: exact fp32 over ONLY the in-window candidates, SEQUENTIAL
// k-order FMA (bitwise-identical arithmetic to the R1 baseline).
// Writes exact d to g_d1.
// ------------------------------------------------------------------
__global__ __launch_bounds__(256) void rescore_kernel(const float* __restrict__ cb) {
    __shared__ float zr[8][512];
    const int lane = threadIdx.x & 31;
    const int w = threadIdx.x >> 5;
    const int total = g_nresc;
    for (int p = blockIdx.x * 8 + w; p < total; p += gridDim.x * 8) {
        const int n = g_resc[p];
        const float thr = g_d1[n] + W_AMB;
        for (int i = lane; i < 128; i += 32)
            *(float4*)&zr[w][i * 4] = *(const float4*)&g_zt[(size_t)n * 512 + i * 4];
        __syncwarp();
        float best = FLT_MAX; int bid = 0x7fffffff;
        #pragma unroll
        for (int j0 = 0; j0 < 2; j0++) {
            int j = j0 * 32 + lane;
            float d = FLT_MAX; int id = 0x7fffffff;
            uint32_t key = (j < 48) ? g_cand[n][j] : 0xFFFFFFFFu;
            if (j < 48 && key_d(key) < thr) {
                id = (int)(key & 0x7FFu);
                const float4* cr4 = (const float4*)(cb + (size_t)id * 512);
                float dot = 0.f;
                #pragma unroll 4
                for (int c4 = 0; c4 < 128; c4++) {
                    float4 v = cr4[c4];
                    dot = fmaf(zr[w][c4 * 4 + 0], v.x, dot);
                    dot = fmaf(zr[w][c4 * 4 + 1], v.y, dot);
                    dot = fmaf(zr[w][c4 * 4 + 2], v.z, dot);
                    dot = fmaf(zr[w][c4 * 4 + 3], v.w, dot);
                }
                d = g_e2[id] - 2.0f * dot;
            }
            if (d < best || (d == best && id < bid)) { best = d; bid = id; }
        }
        #pragma unroll
        for (int o = 16; o; o >>= 1) {
            float od = __shfl_xor_sync(0xffffffffu, best, o);
            int   oi = __shfl_xor_sync(0xffffffffu, bid, o);
            if (od < best || (od == best && oi < bid)) { best = od; bid = oi; }
        }
        if (lane == 0) { g_idx[n] = bid; g_d1[n] = best; }
        __syncwarp();
    }
}

// ------------------------------------------------------------------
// gather: chunked smem staging (64 channels/chunk) + coalesced
// transposed WRITE ONLY (loss comes from d values, no z read).
// ------------------------------------------------------------------
__global__ __launch_bounds__(256) void gather_kernel(
    const float* __restrict__ cb, float* __restrict__ out) {

    __shared__ float  smf[64 * 65];
    __shared__ int    idxs[64];

    const int t  = threadIdx.x;
    const int n0 = blockIdx.x * 64;
    if (t < 64) idxs[t] = g_idx[n0 + t];
    __syncthreads();

    const int b  = n0 >> 12;
    const int hw = n0 & 4095;
    const size_t base = (size_t)b * 512 * 4096 + hw;

    const int m  = t & 63;
    const int c0 = t >> 6;          // 0..3
    const int sr = t >> 4;          // staging row group 0..15
    const int sc = (t & 15) * 4;    // staging channel 0..60

    #pragma unroll 1
    for (int cc = 0; cc < 8; cc++) {
        #pragma unroll
        for (int it = 0; it < 4; it++) {
            int r = it * 16 + sr;
            float4 v = *(const float4*)(cb + (size_t)idxs[r] * 512 + cc * 64 + sc);
            smf[(sc + 0) * 65 + r] = v.x;
            smf[(sc + 1) * 65 + r] = v.y;
            smf[(sc + 2) * 65 + r] = v.z;
            smf[(sc + 3) * 65 + r] = v.w;
        }
        __syncthreads();
        #pragma unroll 4
        for (int i = 0; i < 16; i++) {
            int cl = c0 + i * 4;
            out[base + (size_t)(cc * 64 + cl) * 4096 + m] = smf[cl * 65 + m];
        }
        __syncthreads();
    }
}

// ------------------------------------------------------------------
// loss partials: blocks 0..63 sum g_z2p (16384 each), 64..67 sum g_d1.
// Fixed per-thread partitions + fp64 -> deterministic.
// ------------------------------------------------------------------
__global__ __launch_bounds__(256) void loss_part_kernel() {
    __shared__ double sd[256];
    const int t = threadIdx.x, b = blockIdx.x;
    const float* src = (b < 64) ? (g_z2p + (size_t)b * 16384)
                                : (g_d1 + (size_t)(b - 64) * 16384);
    double a0 = 0, a1 = 0, a2 = 0, a3 = 0;
    for (int i = t * 4; i < 16384; i += 1024) {
        float4 v = *(const float4*)(src + i);
        a0 += v.x; a1 += v.y; a2 += v.z; a3 += v.w;
    }
    sd[t] = (a0 + a1) + (a2 + a3);
    __syncthreads();
    #pragma unroll
    for (int s = 128; s; s >>= 1) {
        if (t < s) sd[t] += sd[t + s];
        __syncthreads();
    }
    if (t == 0) g_partial[b] = sd[0];
}

// ------------------------------------------------------------------
// finalize: loss = 1.25 * (sum_d + sum_z2) / zq_elems
// ------------------------------------------------------------------
__global__ void finalize_kernel(float* __restrict__ out, int out_size, int zq_elems) {
    if (threadIdx.x == 0) {
        double s = 0.0;
        for (int i = 0; i < 68; i++) s += g_partial[i];
        if (out_size > zq_elems)
            out[zq_elems] = (float)(1.25 * s / (double)zq_elems);
    }
}

// ------------------------------------------------------------------
// launch
// ------------------------------------------------------------------
extern "C" void kernel_launch(void* const* d_in, const int* in_sizes, int n_in,
                              void* d_out, int out_size) {
    const float* z  = (const float*)d_in[0];   // [16,512,64,64]
    const float* cb = (const float*)d_in[1];   // [2048,512]
    float* out = (float*)d_out;
    const int zq_elems = in_sizes[0];          // 33554432

    const int SMEM_MAIN = 65536 + 2 * 16384;   // A resident (64KB) + 2 B stages (32KB)
    cudaFuncSetAttribute(vq_mma_kernel,
                         cudaFuncAttributeMaxDynamicSharedMemorySize, SMEM_MAIN);

    prep_cb_kernel<<<1280, 256>>>(cb);                  // launch 0 (e2/bf16 + cbS build)
    prep_z_kernel<<<dim3(2048, 16), dim3(32, 8)>>>(z);  // launch 1
    vq_mma_kernel<<<1024, 256, SMEM_MAIN>>>();          // launch 2
    fixup_kernel<<<512, 256>>>(cb);                     // launch 3 -> profiled
    rescore_kernel<<<512, 256>>>(cb);                   // launch 4
    gather_kernel<<<1024, 256>>>(cb, out);              // launch 5
    loss_part_kernel<<<68, 256>>>();                    // launch 6
    finalize_kernel<<<1, 32>>>(out, out_size, zq_elems);// launch 7
}

// round 15
// speedup vs baseline: 1.1947x; 1.0307x over previous
#include <cuda_runtime.h>
#include <cuda_bf16.h>
#include <cstdint>
#include <cfloat>

// ------------------------------------------------------------------
// device scratch (static — no allocs allowed)
// ------------------------------------------------------------------
__device__ __nv_bfloat16 g_zhi[65536ull * 512];   // bf16(z) transposed [n][c]
__device__ float         g_zt [65536ull * 512];   // fp32 z transposed [n][c]
__device__ __nv_bfloat16 g_cbhi[2048ull * 512];   // bf16(codebook) [e][c]
__device__ float    g_cbS[16ull * 512 * 128];     // fp32 codebook slot-major [q][c][i]
__device__ float    g_e2[2048];                   // fp32 ||e||^2 (warp-tree, same as R1)
__device__ int      g_idx[65536];
__device__ uint32_t g_cand[65536][48];            // packed keys: (q(d)<<11)|idx
__device__ float    g_d1[65536];                  // d_kernel of selected code (exact after rescore/fixup)
__device__ float    g_z2p[16ull * 65536];         // per-(cblock,pixel) ||z||^2 partials
__device__ int      g_resc[65536];
__device__ int      g_nresc;
__device__ int      g_fix[65536];                 // packed (n<<16)|slot_mask
__device__ int      g_nfix;
__device__ double   g_partial[1024];

static constexpr float W_AMB  = 0.52f;  // ~7 sigma bf16 noise + key quantization margin
static constexpr float INV256 = 1.0f / 256.0f;

// ------------------------------------------------------------------
// PTX helpers (baseline PTX only — no tcgen05 on this toolchain target)
// ------------------------------------------------------------------
__device__ __forceinline__ uint32_t smem_u32(const void* p) {
    uint32_t a;
    asm("{ .reg .u64 t; cvta.to.shared.u64 t, %1; cvt.u32.u64 %0, t; }" : "=r"(a) : "l"(p));
    return a;
}
__device__ __forceinline__ void cp16(uint32_t dst, const void* src) {
    uint64_t g = __cvta_generic_to_global(src);
    asm volatile("cp.async.cg.shared.global [%0], [%1], 16;" :: "r"(dst), "l"(g) : "memory");
}
#define CP_COMMIT() asm volatile("cp.async.commit_group;" ::: "memory")
#define CP_WAIT(N)  asm volatile("cp.async.wait_group %0;" :: "n"(N) : "memory")

__device__ __forceinline__ uint32_t swz(uint32_t x) { return x ^ ((x >> 3) & 0x70); }

__device__ __forceinline__ void ldsm4(uint32_t& r0, uint32_t& r1, uint32_t& r2, uint32_t& r3,
                                      uint32_t addr) {
    asm volatile("ldmatrix.sync.aligned.m8n8.x4.shared.b16 {%0,%1,%2,%3}, [%4];"
                 : "=r"(r0), "=r"(r1), "=r"(r2), "=r"(r3) : "r"(addr));
}
__device__ __forceinline__ void mma16816(float& c0, float& c1, float& c2, float& c3,
                                         uint32_t a0, uint32_t a1, uint32_t a2, uint32_t a3,
                                         uint32_t b0, uint32_t b1) {
    asm volatile("mma.sync.aligned.m16n8k16.row.col.f32.bf16.bf16.f32 "
                 "{%0,%1,%2,%3}, {%4,%5,%6,%7}, {%8,%9}, {%0,%1,%2,%3};"
                 : "+f"(c0), "+f"(c1), "+f"(c2), "+f"(c3)
                 : "r"(a0), "r"(a1), "r"(a2), "r"(a3), "r"(b0), "r"(b1));
}

// packed key helpers: key = (round(max(d,0)*256) << 11) | idx ; smaller = better,
// exact-tie resolves to lower idx automatically.
__device__ __forceinline__ uint32_t pack_key(float d, int idx) {
    return (__float2uint_rn(fmaxf(d, 0.0f) * 256.0f) << 11) | (uint32_t)idx;
}
__device__ __forceinline__ float key_d(uint32_t k) { return (float)(k >> 11) * INV256; }

// slot q, in-slot index i (ascending i <-> ascending code id)
__device__ __forceinline__ int slot_code(int q, int i) {
    return ((i >> 3) << 7) + ((q >> 2) << 5) + (((i >> 1) & 3) << 3) + ((q & 3) << 1) + (i & 1);
}

// branchless top-3 insert on packed keys (6 umin/umax)
#define INS_PK(S, K) do {                                                      \
    uint32_t _h0 = max(tk[S][0], (K)); tk[S][0] = min(tk[S][0], (K));          \
    uint32_t _h1 = max(tk[S][1], _h0); tk[S][1] = min(tk[S][1], _h0);          \
    tk[S][2] = min(tk[S][2], _h1);                                             \
} while (0)

// ------------------------------------------------------------------
// prep: blocks [0,256): codebook -> bf16 + fp32 ||e||^2 (R1 arithmetic);
//       blocks [256,1280): build slot-major codebook g_cbS
// ------------------------------------------------------------------
__global__ __launch_bounds__(256) void prep_cb_kernel(const float* __restrict__ cb) {
    if (blockIdx.x == 0 && threadIdx.x == 0) { g_nfix = 0; g_nresc = 0; }

    if (blockIdx.x < 256) {
        int warp = (blockIdx.x * blockDim.x + threadIdx.x) >> 5;
        int lane = threadIdx.x & 31;
        const float* row = cb + (size_t)warp * 512;
        float s = 0.f;
        #pragma unroll 4
        for (int c = lane; c < 512; c += 32) {
            float v = row[c];
            s += v * v;
            g_cbhi[(size_t)warp * 512 + c] = __float2bfloat16(v);
        }
        #pragma unroll
        for (int o = 16; o; o >>= 1) s += __shfl_xor_sync(0xffffffffu, s, o);
        if (lane == 0) g_e2[warp] = s;
    } else {
        // cbS: flat = ((q*512)+c)*128 + i ; coalesced writes, scattered reads
        const int tb = blockIdx.x - 256;            // 0..1023
        int flat0 = tb * 1024 + threadIdx.x;
        #pragma unroll
        for (int it = 0; it < 4; it++) {
            int flat = flat0 + it * 256;
            int i = flat & 127;
            int c = (flat >> 7) & 511;
            int q = flat >> 16;
            int e = slot_code(q, i);
            g_cbS[flat] = cb[(size_t)e * 512 + c];
        }
    }
}

// ------------------------------------------------------------------
// prep: z [B,C,H,W] -> transposed bf16 + fp32 planes [n][c] + ||z||^2 partials
// ------------------------------------------------------------------
__global__ __launch_bounds__(256) void prep_z_kernel(const float* __restrict__ z) {
    __shared__ float s[32][33];
    const int tx = threadIdx.x, ty = threadIdx.y;
    const int n0 = blockIdx.x * 32;
    const int c0 = blockIdx.y * 32;
    const int b  = n0 >> 12;
    const int hw = n0 & 4095;
    #pragma unroll
    for (int i = 0; i < 4; i++) {
        int c = c0 + ty + i * 8;
        s[ty + i * 8][tx] = z[((size_t)b * 512 + c) * 4096 + hw + tx];
    }
    __syncthreads();
    #pragma unroll
    for (int i = 0; i < 4; i++) {
        float v = s[tx][ty + i * 8];      // pixel n0+ty+i*8, channel c0+tx
        size_t idx = (size_t)(n0 + ty + i * 8) * 512 + c0 + tx;
        g_zhi[idx] = __float2bfloat16(v);
        g_zt[idx]  = v;
        float sq = v * v;                 // reduce over tx = 32 channels
        #pragma unroll
        for (int o = 16; o; o >>= 1) sq += __shfl_xor_sync(0xffffffffu, sq, o);
        if (tx == 0) g_z2p[(size_t)blockIdx.y * 65536 + n0 + ty + i * 8] = sq;
    }
}

// ------------------------------------------------------------------
// main: HMMA distance GEMM + windowed packed-top-3 candidate tracking
// CTA: 64 pixels x 2048 codes, 256 threads (8 warps), 2 CTAs/SM.
// Warps as 2(M) x 4(N); warp tile 32x32. A resident (64KB), B 2-stage (32KB).
// ks loop software-pipelined with double-buffered LDSM fragments.
// ------------------------------------------------------------------
__global__ __launch_bounds__(256, 2) void vq_mma_kernel() {
    extern __shared__ char sm[];
    const uint32_t sA = smem_u32(sm);           // 64KB: 8 kt-tiles of [64m][128B]
    const uint32_t sB = sA + 65536u;            // 2 stages x 16KB
    uint32_t* candk = (uint32_t*)sm;            // merge reuse: [64][48]

    const int t = threadIdx.x;
    const int lane = t & 31;
    const int w = t >> 5;
    const int wm = w >> 2;      // 0..1  (M, 32 rows each)
    const int wn = w & 3;       // 0..3  (N, 32 cols each)
    const int n0 = blockIdx.x * 64;

    // ---- A resident load (once): 4096 16B-units over 256 threads ----
    #pragma unroll
    for (int i = 0; i < 16; i++) {
        int U = t + 256 * i;
        int m = U >> 6, r = U & 63;             // r = kt*8 + j
        int kt = r >> 3, j = r & 7;
        cp16(sA + (uint32_t)kt * 8192u + swz((uint32_t)m * 128u + (uint32_t)j * 16u),
             g_zhi + ((size_t)(n0 + m)) * 512 + r * 8);
    }
    CP_COMMIT();

    auto loadB = [&](int c) {
        int nt = c >> 3, kt = c & 7, s = c & 1;
        #pragma unroll
        for (int i = 0; i < 4; i++) {
            int U = t + 256 * i;
            int n = U >> 3, j = U & 7;
            cp16(sB + (uint32_t)s * 16384u + swz((uint32_t)n * 128u + (uint32_t)j * 16u),
                 g_cbhi + ((size_t)(nt * 128 + n)) * 512 + kt * 64 + j * 8);
        }
    };
    loadB(0);
    CP_COMMIT();

    // fragment double buffers + packed top-3 per row-slot
    uint32_t aF[2][2][4], bF[2][2][4];
    float acc[2][4][4];
    uint32_t tk[4][3];
    #pragma unroll
    for (int s = 0; s < 4; s++)
        #pragma unroll
        for (int k = 0; k < 3; k++) tk[s][k] = 0xFFFFFFFFu;

    const int am  = ((lane >> 3) & 1) * 8 + (lane & 7);
    const int akO = (lane >> 4) * 16;
    const int bn  = (lane >> 4) * 8 + (lane & 7);
    const int bkO = ((lane >> 3) & 1) * 16;

    for (int c = 0; c < 128; c++) {
        const int nt = c >> 3, kt = c & 7, s = c & 1;

        CP_WAIT(0);
        __syncthreads();
        if (c + 1 < 128) { loadB(c + 1); CP_COMMIT(); }

        if (kt == 0) {
            #pragma unroll
            for (int f = 0; f < 2; f++)
                #pragma unroll
                for (int g = 0; g < 4; g++)
                    #pragma unroll
                    for (int q = 0; q < 4; q++) acc[f][g][q] = 0.f;
        }

        const uint32_t aT = sA + (uint32_t)kt * 8192u;
        const uint32_t bT = sB + (uint32_t)s * 16384u;

        auto ldA = [&](int buf, int ks) {
            #pragma unroll
            for (int f = 0; f < 2; f++) {
                uint32_t off = (uint32_t)((wm * 32 + f * 16 + am) * 128 + ks * 32 + akO);
                ldsm4(aF[buf][f][0], aF[buf][f][1], aF[buf][f][2], aF[buf][f][3],
                      aT + swz(off));
            }
        };
        auto ldB = [&](int buf, int ks) {
            #pragma unroll
            for (int g2 = 0; g2 < 2; g2++) {
                uint32_t off = (uint32_t)((wn * 32 + g2 * 16 + bn) * 128 + ks * 32 + bkO);
                ldsm4(bF[buf][g2][0], bF[buf][g2][1], bF[buf][g2][2], bF[buf][g2][3],
                      bT + swz(off));
            }
        };

        // software-pipelined ks loop: prefetch ks+1 fragments before MMAs of ks
        ldA(0, 0); ldB(0, 0);
        #pragma unroll
        for (int ks = 0; ks < 4; ks++) {
            const int cur = ks & 1, nxt = cur ^ 1;
            if (ks < 3) { ldA(nxt, ks + 1); ldB(nxt, ks + 1); }
            #pragma unroll
            for (int f = 0; f < 2; f++)
                #pragma unroll
                for (int g = 0; g < 4; g++)
                    mma16816(acc[f][g][0], acc[f][g][1], acc[f][g][2], acc[f][g][3],
                             aF[cur][f][0], aF[cur][f][1], aF[cur][f][2], aF[cur][f][3],
                             bF[cur][g >> 1][(g & 1) * 2], bF[cur][g >> 1][(g & 1) * 2 + 1]);
        }

        if (kt == 7) {
            #pragma unroll
            for (int f = 0; f < 2; f++) {
                #pragma unroll
                for (int g = 0; g < 4; g++) {
                    int nfirst = nt * 128 + wn * 32 + g * 8 + (lane & 3) * 2;
                    float e2a = g_e2[nfirst], e2b = g_e2[nfirst + 1];
                    uint32_t k0 = pack_key(e2a - 2.0f * acc[f][g][0], nfirst);
                    uint32_t k1 = pack_key(e2b - 2.0f * acc[f][g][1], nfirst + 1);
                    uint32_t k2 = pack_key(e2a - 2.0f * acc[f][g][2], nfirst);
                    uint32_t k3 = pack_key(e2b - 2.0f * acc[f][g][3], nfirst + 1);
                    INS_PK(2 * f,     k0);
                    INS_PK(2 * f,     k1);
                    INS_PK(2 * f + 1, k2);
                    INS_PK(2 * f + 1, k3);
                }
            }
        }
    }
    __syncthreads();   // all warps done reading sA/sB before candk aliases them

    // ---- merge: 16 thread-slots x top-3 = 48 packed candidates per pixel row ----
    const int tslot = wn * 4 + (lane & 3);      // 0..15
    #pragma unroll
    for (int f = 0; f < 2; f++) {
        #pragma unroll
        for (int h = 0; h < 2; h++) {
            int row = wm * 32 + f * 16 + h * 8 + (lane >> 2);
            #pragma unroll
            for (int k = 0; k < 3; k++)
                candk[row * 48 + tslot * 3 + k] = tk[2 * f + h][k];
        }
    }
    __syncthreads();

    if (t < 64) {
        const int row = t;
        const int n = n0 + row;
        uint32_t k1 = 0xFFFFFFFFu, k2 = 0xFFFFFFFFu;
        #pragma unroll 4
        for (int j = 0; j < 48; j++) {
            uint32_t k = candk[row * 48 + j];
            uint32_t hi = max(k, k1);
            k1 = min(k, k1);
            k2 = min(hi, k2);
        }
        const float d1 = key_d(k1), d2 = key_d(k2);
        // per-slot overflow mask: slot q may have dropped in-window candidates
        // only if its 3rd-best is itself in-window
        uint32_t mask = 0;
        #pragma unroll
        for (int q = 0; q < 16; q++)
            if (key_d(candk[row * 48 + q * 3 + 2]) < d1 + W_AMB) mask |= (1u << q);
        g_idx[n] = (int)(k1 & 0x7FFu);
        g_d1[n] = d1;
        #pragma unroll 4
        for (int j = 0; j < 48; j++) g_cand[n][j] = candk[row * 48 + j];
        if (mask) {
            int p = atomicAdd(&g_nfix, 1);
            g_fix[p] = (int)(((uint32_t)n << 16) | mask);
        } else if (d2 - d1 < W_AMB) {
            int p = atomicAdd(&g_nresc, 1);
            g_resc[p] = n;
        }
    }
}

// ------------------------------------------------------------------
// fixup: warp per flagged pixel. Exact argmin over (IN-WINDOW candidates)
// U (full 128-code sets of flagged slots, via slot-major g_cbS with
// coalesced loads). Window filter on part A: any candidate with approx
// d >= d1+W has exact d > exact-min (W >= 2*noise) -> provably skippable.
// Per-code dot = SEQUENTIAL c-order fmaf (R1 numerics).
// ------------------------------------------------------------------
__global__ __launch_bounds__(256) void fixup_kernel(const float* __restrict__ cb) {
    __shared__ float zr[8][512];
    const int lane = threadIdx.x & 31;
    const int w = threadIdx.x >> 5;
    const int total = g_nfix;
    for (int p = blockIdx.x * 8 + w; p < total; p += gridDim.x * 8) {
        const uint32_t rec = (uint32_t)g_fix[p];
        const int n = (int)(rec >> 16);
        uint32_t mask = rec & 0xFFFFu;
        const float thr = g_d1[n] + W_AMB;
        for (int i = lane; i < 128; i += 32)
            *(float4*)&zr[w][i * 4] = *(const float4*)&g_zt[(size_t)n * 512 + i * 4];
        __syncwarp();

        float best = FLT_MAX; int bid = 0x7fffffff;

        // part A: ONLY in-window candidates, exact (typically 2-4 of 48)
        #pragma unroll
        for (int j0 = 0; j0 < 2; j0++) {
            int j = j0 * 32 + lane;
            uint32_t key = (j < 48) ? g_cand[n][j] : 0xFFFFFFFFu;
            if (j < 48 && key_d(key) < thr) {
                int id = (int)(key & 0x7FFu);
                const float4* cr4 = (const float4*)(cb + (size_t)id * 512);
                float dot = 0.f;
                #pragma unroll 4
                for (int c4 = 0; c4 < 128; c4++) {
                    float4 v = cr4[c4];
                    dot = fmaf(zr[w][c4 * 4 + 0], v.x, dot);
                    dot = fmaf(zr[w][c4 * 4 + 1], v.y, dot);
                    dot = fmaf(zr[w][c4 * 4 + 2], v.z, dot);
                    dot = fmaf(zr[w][c4 * 4 + 3], v.w, dot);
                }
                float d = g_e2[id] - 2.0f * dot;
                if (d < best || (d == best && id < bid)) { best = d; bid = id; }
            }
        }

        // part B: flagged slots, 4 codes/lane, coalesced slot-major loads
        while (mask) {
            int q = __ffs(mask) - 1; mask &= (mask - 1);
            const float* basep = g_cbS + ((size_t)q * 512) * 128 + lane * 4;
            float dot0 = 0.f, dot1 = 0.f, dot2 = 0.f, dot3 = 0.f;
            #pragma unroll 4
            for (int c = 0; c < 512; c++) {
                float zv = zr[w][c];
                float4 v = *(const float4*)(basep + (size_t)c * 128);
                dot0 = fmaf(zv, v.x, dot0);
                dot1 = fmaf(zv, v.y, dot1);
                dot2 = fmaf(zv, v.z, dot2);
                dot3 = fmaf(zv, v.w, dot3);
            }
            float dots[4] = { dot0, dot1, dot2, dot3 };
            #pragma unroll
            for (int j = 0; j < 4; j++) {
                int e = slot_code(q, lane * 4 + j);
                float d = g_e2[e] - 2.0f * dots[j];
                if (d < best || (d == best && e < bid)) { best = d; bid = e; }
            }
        }

        #pragma unroll
        for (int o = 16; o; o >>= 1) {
            float od = __shfl_xor_sync(0xffffffffu, best, o);
            int   oi = __shfl_xor_sync(0xffffffffu, bid, o);
            if (od < best || (od == best && oi < bid)) { best = od; bid = oi; }
        }
        if (lane == 0) { g_idx[n] = bid; g_d1[n] = best; }
        __syncwarp();
    }
}

// ------------------------------------------------------------------
// rescore: exact fp32 over ONLY the in-window candidates, SEQUENTIAL
// k-order FMA (bitwise-identical arithmetic to the R1 baseline).
// Writes exact d to g_d1.
// ------------------------------------------------------------------
__global__ __launch_bounds__(256) void rescore_kernel(const float* __restrict__ cb) {
    __shared__ float zr[8][512];
    const int lane = threadIdx.x & 31;
    const int w = threadIdx.x >> 5;
    const int total = g_nresc;
    for (int p = blockIdx.x * 8 + w; p < total; p += gridDim.x * 8) {
        const int n = g_resc[p];
        const float thr = g_d1[n] + W_AMB;
        for (int i = lane; i < 128; i += 32)
            *(float4*)&zr[w][i * 4] = *(const float4*)&g_zt[(size_t)n * 512 + i * 4];
        __syncwarp();
        float best = FLT_MAX; int bid = 0x7fffffff;
        #pragma unroll
        for (int j0 = 0; j0 < 2; j0++) {
            int j = j0 * 32 + lane;
            float d = FLT_MAX; int id = 0x7fffffff;
            uint32_t key = (j < 48) ? g_cand[n][j] : 0xFFFFFFFFu;
            if (j < 48 && key_d(key) < thr) {
                id = (int)(key & 0x7FFu);
                const float4* cr4 = (const float4*)(cb + (size_t)id * 512);
                float dot = 0.f;
                #pragma unroll 4
                for (int c4 = 0; c4 < 128; c4++) {
                    float4 v = cr4[c4];
                    dot = fmaf(zr[w][c4 * 4 + 0], v.x, dot);
                    dot = fmaf(zr[w][c4 * 4 + 1], v.y, dot);
                    dot = fmaf(zr[w][c4 * 4 + 2], v.z, dot);
                    dot = fmaf(zr[w][c4 * 4 + 3], v.w, dot);
                }
                d = g_e2[id] - 2.0f * dot;
            }
            if (d < best || (d == best && id < bid)) { best = d; bid = id; }
        }
        #pragma unroll
        for (int o = 16; o; o >>= 1) {
            float od = __shfl_xor_sync(0xffffffffu, best, o);
            int   oi = __shfl_xor_sync(0xffffffffu, bid, o);
            if (od < best || (od == best && oi < bid)) { best = od; bid = oi; }
        }
        if (lane == 0) { g_idx[n] = bid; g_d1[n] = best; }
        __syncwarp();
    }
}

// ------------------------------------------------------------------
// gather: chunked smem staging (64 channels/chunk) + coalesced
// transposed WRITE ONLY (loss comes from d values, no z read).
// ------------------------------------------------------------------
__global__ __launch_bounds__(256) void gather_kernel(
    const float* __restrict__ cb, float* __restrict__ out) {

    __shared__ float  smf[64 * 65];
    __shared__ int    idxs[64];

    const int t  = threadIdx.x;
    const int n0 = blockIdx.x * 64;
    if (t < 64) idxs[t] = g_idx[n0 + t];
    __syncthreads();

    const int b  = n0 >> 12;
    const int hw = n0 & 4095;
    const size_t base = (size_t)b * 512 * 4096 + hw;

    const int m  = t & 63;
    const int c0 = t >> 6;          // 0..3
    const int sr = t >> 4;          // staging row group 0..15
    const int sc = (t & 15) * 4;    // staging channel 0..60

    #pragma unroll 1
    for (int cc = 0; cc < 8; cc++) {
        #pragma unroll
        for (int it = 0; it < 4; it++) {
            int r = it * 16 + sr;
            float4 v = *(const float4*)(cb + (size_t)idxs[r] * 512 + cc * 64 + sc);
            smf[(sc + 0) * 65 + r] = v.x;
            smf[(sc + 1) * 65 + r] = v.y;
            smf[(sc + 2) * 65 + r] = v.z;
            smf[(sc + 3) * 65 + r] = v.w;
        }
        __syncthreads();
        #pragma unroll 4
        for (int i = 0; i < 16; i++) {
            int cl = c0 + i * 4;
            out[base + (size_t)(cc * 64 + cl) * 4096 + m] = smf[cl * 65 + m];
        }
        __syncthreads();
    }
}

// ------------------------------------------------------------------
// loss partials: blocks 0..63 sum g_z2p (16384 each), 64..67 sum g_d1.
// Fixed per-thread partitions + fp64 -> deterministic.
// ------------------------------------------------------------------
__global__ __launch_bounds__(256) void loss_part_kernel() {
    __shared__ double sd[256];
    const int t = threadIdx.x, b = blockIdx.x;
    const float* src = (b < 64) ? (g_z2p + (size_t)b * 16384)
                                : (g_d1 + (size_t)(b - 64) * 16384);
    double a0 = 0, a1 = 0, a2 = 0, a3 = 0;
    for (int i = t * 4; i < 16384; i += 1024) {
        float4 v = *(const float4*)(src + i);
        a0 += v.x; a1 += v.y; a2 += v.z; a3 += v.w;
    }
    sd[t] = (a0 + a1) + (a2 + a3);
    __syncthreads();
    #pragma unroll
    for (int s = 128; s; s >>= 1) {
        if (t < s) sd[t] += sd[t + s];
        __syncthreads();
    }
    if (t == 0) g_partial[b] = sd[0];
}

// ------------------------------------------------------------------
// finalize: loss = 1.25 * (sum_d + sum_z2) / zq_elems
// ------------------------------------------------------------------
__global__ void finalize_kernel(float* __restrict__ out, int out_size, int zq_elems) {
    if (threadIdx.x == 0) {
        double s = 0.0;
        for (int i = 0; i < 68; i++) s += g_partial[i];
        if (out_size > zq_elems)
            out[zq_elems] = (float)(1.25 * s / (double)zq_elems);
    }
}

// ------------------------------------------------------------------
// launch
// ------------------------------------------------------------------
extern "C" void kernel_launch(void* const* d_in, const int* in_sizes, int n_in,
                              void* d_out, int out_size) {
    const float* z  = (const float*)d_in[0];   // [16,512,64,64]
    const float* cb = (const float*)d_in[1];   // [2048,512]
    float* out = (float*)d_out;
    const int zq_elems = in_sizes[0];          // 33554432

    const int SMEM_MAIN = 65536 + 2 * 16384;   // A resident (64KB) + 2 B stages (32KB)
    cudaFuncSetAttribute(vq_mma_kernel,
                         cudaFuncAttributeMaxDynamicSharedMemorySize, SMEM_MAIN);

    prep_cb_kernel<<<1280, 256>>>(cb);                  // launch 0 (e2/bf16 + cbS build)
    prep_z_kernel<<<dim3(2048, 16), dim3(32, 8)>>>(z);  // launch 1
    vq_mma_kernel<<<1024, 256, SMEM_MAIN>>>();          // launch 2
    fixup_kernel<<<512, 256>>>(cb);                     // launch 3 -> profiled
    rescore_kernel<<<512, 256>>>(cb);                   // launch 4
    gather_kernel<<<1024, 256>>>(cb, out);              // launch 5
    loss_part_kernel<<<68, 256>>>();                    // launch 6
    finalize_kernel<<<1, 32>>>(out, out_size, zq_elems);// launch 7
}

// round 16
// speedup vs baseline: 1.4537x; 1.2167x over previous
#include <cuda_runtime.h>
#include <cuda_bf16.h>
#include <cstdint>
#include <cfloat>

// ------------------------------------------------------------------
// device scratch (static — no allocs allowed)
// ------------------------------------------------------------------
__device__ __nv_bfloat16 g_zhi[65536ull * 512];   // bf16(z) transposed [n][c]
__device__ float         g_zt [65536ull * 512];   // fp32 z transposed [n][c]
__device__ __nv_bfloat16 g_cbhi[2048ull * 512];   // bf16(codebook) [e][c]
__device__ float    g_cbS[16ull * 512 * 128];     // fp32 codebook slot-major [q][c][i]
__device__ float    g_e2[2048];                   // fp32 ||e||^2 (warp-tree, same as R1)
__device__ int      g_idx[65536];
__device__ uint32_t g_cand[65536][64];            // packed keys: 16 slots x top-4
__device__ float    g_d1[65536];                  // d_kernel of selected code (exact after rescore/fixup)
__device__ float    g_z2p[16ull * 65536];         // per-(cblock,pixel) ||z||^2 partials
__device__ int      g_resc[65536];
__device__ int      g_nresc;
__device__ int      g_fix[65536];                 // packed (n<<16)|slot_mask
__device__ int      g_nfix;
__device__ double   g_partial[1024];

static constexpr float W_AMB  = 0.52f;  // ~7 sigma bf16 noise + key quantization margin
static constexpr float INV256 = 1.0f / 256.0f;

// ------------------------------------------------------------------
// PTX helpers (baseline PTX only — no tcgen05 on this toolchain target)
// ------------------------------------------------------------------
__device__ __forceinline__ uint32_t smem_u32(const void* p) {
    uint32_t a;
    asm("{ .reg .u64 t; cvta.to.shared.u64 t, %1; cvt.u32.u64 %0, t; }" : "=r"(a) : "l"(p));
    return a;
}
__device__ __forceinline__ void cp16(uint32_t dst, const void* src) {
    uint64_t g = __cvta_generic_to_global(src);
    asm volatile("cp.async.cg.shared.global [%0], [%1], 16;" :: "r"(dst), "l"(g) : "memory");
}
#define CP_COMMIT() asm volatile("cp.async.commit_group;" ::: "memory")
#define CP_WAIT(N)  asm volatile("cp.async.wait_group %0;" :: "n"(N) : "memory")

__device__ __forceinline__ uint32_t swz(uint32_t x) { return x ^ ((x >> 3) & 0x70); }

__device__ __forceinline__ void ldsm4(uint32_t& r0, uint32_t& r1, uint32_t& r2, uint32_t& r3,
                                      uint32_t addr) {
    asm volatile("ldmatrix.sync.aligned.m8n8.x4.shared.b16 {%0,%1,%2,%3}, [%4];"
                 : "=r"(r0), "=r"(r1), "=r"(r2), "=r"(r3) : "r"(addr));
}
__device__ __forceinline__ void mma16816(float& c0, float& c1, float& c2, float& c3,
                                         uint32_t a0, uint32_t a1, uint32_t a2, uint32_t a3,
                                         uint32_t b0, uint32_t b1) {
    asm volatile("mma.sync.aligned.m16n8k16.row.col.f32.bf16.bf16.f32 "
                 "{%0,%1,%2,%3}, {%4,%5,%6,%7}, {%8,%9}, {%0,%1,%2,%3};"
                 : "+f"(c0), "+f"(c1), "+f"(c2), "+f"(c3)
                 : "r"(a0), "r"(a1), "r"(a2), "r"(a3), "r"(b0), "r"(b1));
}

// packed key helpers: key = (round(max(d,0)*256) << 11) | idx ; smaller = better,
// exact-tie resolves to lower idx automatically.
__device__ __forceinline__ uint32_t pack_key(float d, int idx) {
    return (__float2uint_rn(fmaxf(d, 0.0f) * 256.0f) << 11) | (uint32_t)idx;
}
__device__ __forceinline__ float key_d(uint32_t k) { return (float)(k >> 11) * INV256; }

// slot q, in-slot index i (ascending i <-> ascending code id)
__device__ __forceinline__ int slot_code(int q, int i) {
    return ((i >> 3) << 7) + ((q >> 2) << 5) + (((i >> 1) & 3) << 3) + ((q & 3) << 1) + (i & 1);
}

// branchless top-4 insert on packed keys (8 umin/umax)
#define INS_PK(S, K) do {                                                      \
    uint32_t _h0 = max(tk[S][0], (K)); tk[S][0] = min(tk[S][0], (K));          \
    uint32_t _h1 = max(tk[S][1], _h0); tk[S][1] = min(tk[S][1], _h0);          \
    uint32_t _h2 = max(tk[S][2], _h1); tk[S][2] = min(tk[S][2], _h1);          \
    tk[S][3] = min(tk[S][3], _h2);                                             \
} while (0)

// ------------------------------------------------------------------
// prep: blocks [0,256): codebook -> bf16 + fp32 ||e||^2 (R1 arithmetic);
//       blocks [256,1280): build slot-major codebook g_cbS
// ------------------------------------------------------------------
__global__ __launch_bounds__(256) void prep_cb_kernel(const float* __restrict__ cb) {
    if (blockIdx.x == 0 && threadIdx.x == 0) { g_nfix = 0; g_nresc = 0; }

    if (blockIdx.x < 256) {
        int warp = (blockIdx.x * blockDim.x + threadIdx.x) >> 5;
        int lane = threadIdx.x & 31;
        const float* row = cb + (size_t)warp * 512;
        float s = 0.f;
        #pragma unroll 4
        for (int c = lane; c < 512; c += 32) {
            float v = row[c];
            s += v * v;
            g_cbhi[(size_t)warp * 512 + c] = __float2bfloat16(v);
        }
        #pragma unroll
        for (int o = 16; o; o >>= 1) s += __shfl_xor_sync(0xffffffffu, s, o);
        if (lane == 0) g_e2[warp] = s;
    } else {
        // cbS: flat = ((q*512)+c)*128 + i ; coalesced writes, scattered reads
        const int tb = blockIdx.x - 256;            // 0..1023
        int flat0 = tb * 1024 + threadIdx.x;
        #pragma unroll
        for (int it = 0; it < 4; it++) {
            int flat = flat0 + it * 256;
            int i = flat & 127;
            int c = (flat >> 7) & 511;
            int q = flat >> 16;
            int e = slot_code(q, i);
            g_cbS[flat] = cb[(size_t)e * 512 + c];
        }
    }
}

// ------------------------------------------------------------------
// prep: z [B,C,H,W] -> transposed bf16 + fp32 planes [n][c] + ||z||^2 partials
// ------------------------------------------------------------------
__global__ __launch_bounds__(256) void prep_z_kernel(const float* __restrict__ z) {
    __shared__ float s[32][33];
    const int tx = threadIdx.x, ty = threadIdx.y;
    const int n0 = blockIdx.x * 32;
    const int c0 = blockIdx.y * 32;
    const int b  = n0 >> 12;
    const int hw = n0 & 4095;
    #pragma unroll
    for (int i = 0; i < 4; i++) {
        int c = c0 + ty + i * 8;
        s[ty + i * 8][tx] = z[((size_t)b * 512 + c) * 4096 + hw + tx];
    }
    __syncthreads();
    #pragma unroll
    for (int i = 0; i < 4; i++) {
        float v = s[tx][ty + i * 8];      // pixel n0+ty+i*8, channel c0+tx
        size_t idx = (size_t)(n0 + ty + i * 8) * 512 + c0 + tx;
        g_zhi[idx] = __float2bfloat16(v);
        g_zt[idx]  = v;
        float sq = v * v;                 // reduce over tx = 32 channels
        #pragma unroll
        for (int o = 16; o; o >>= 1) sq += __shfl_xor_sync(0xffffffffu, sq, o);
        if (tx == 0) g_z2p[(size_t)blockIdx.y * 65536 + n0 + ty + i * 8] = sq;
    }
}

// ------------------------------------------------------------------
// main: HMMA distance GEMM + windowed packed-top-4 candidate tracking
// CTA: 64 pixels x 2048 codes, 256 threads (8 warps), 2 CTAs/SM.
// Warps as 2(M) x 4(N); warp tile 32x32. A resident (64KB), B 2-stage (32KB).
// ks loop software-pipelined with double-buffered LDSM fragments.
// ------------------------------------------------------------------
__global__ __launch_bounds__(256, 2) void vq_mma_kernel() {
    extern __shared__ char sm[];
    const uint32_t sA = smem_u32(sm);           // 64KB: 8 kt-tiles of [64m][128B]
    const uint32_t sB = sA + 65536u;            // 2 stages x 16KB
    uint32_t* candk = (uint32_t*)sm;            // merge reuse: [64][65] padded

    const int t = threadIdx.x;
    const int lane = t & 31;
    const int w = t >> 5;
    const int wm = w >> 2;      // 0..1  (M, 32 rows each)
    const int wn = w & 3;       // 0..3  (N, 32 cols each)
    const int n0 = blockIdx.x * 64;

    // ---- A resident load (once): 4096 16B-units over 256 threads ----
    #pragma unroll
    for (int i = 0; i < 16; i++) {
        int U = t + 256 * i;
        int m = U >> 6, r = U & 63;             // r = kt*8 + j
        int kt = r >> 3, j = r & 7;
        cp16(sA + (uint32_t)kt * 8192u + swz((uint32_t)m * 128u + (uint32_t)j * 16u),
             g_zhi + ((size_t)(n0 + m)) * 512 + r * 8);
    }
    CP_COMMIT();

    auto loadB = [&](int c) {
        int nt = c >> 3, kt = c & 7, s = c & 1;
        #pragma unroll
        for (int i = 0; i < 4; i++) {
            int U = t + 256 * i;
            int n = U >> 3, j = U & 7;
            cp16(sB + (uint32_t)s * 16384u + swz((uint32_t)n * 128u + (uint32_t)j * 16u),
                 g_cbhi + ((size_t)(nt * 128 + n)) * 512 + kt * 64 + j * 8);
        }
    };
    loadB(0);
    CP_COMMIT();

    // fragment double buffers + packed top-4 per row-slot
    uint32_t aF[2][2][4], bF[2][2][4];
    float acc[2][4][4];
    uint32_t tk[4][4];
    #pragma unroll
    for (int s = 0; s < 4; s++)
        #pragma unroll
        for (int k = 0; k < 4; k++) tk[s][k] = 0xFFFFFFFFu;

    const int am  = ((lane >> 3) & 1) * 8 + (lane & 7);
    const int akO = (lane >> 4) * 16;
    const int bn  = (lane >> 4) * 8 + (lane & 7);
    const int bkO = ((lane >> 3) & 1) * 16;

    for (int c = 0; c < 128; c++) {
        const int nt = c >> 3, kt = c & 7, s = c & 1;

        CP_WAIT(0);
        __syncthreads();
        if (c + 1 < 128) { loadB(c + 1); CP_COMMIT(); }

        if (kt == 0) {
            #pragma unroll
            for (int f = 0; f < 2; f++)
                #pragma unroll
                for (int g = 0; g < 4; g++)
                    #pragma unroll
                    for (int q = 0; q < 4; q++) acc[f][g][q] = 0.f;
        }

        const uint32_t aT = sA + (uint32_t)kt * 8192u;
        const uint32_t bT = sB + (uint32_t)s * 16384u;

        auto ldA = [&](int buf, int ks) {
            #pragma unroll
            for (int f = 0; f < 2; f++) {
                uint32_t off = (uint32_t)((wm * 32 + f * 16 + am) * 128 + ks * 32 + akO);
                ldsm4(aF[buf][f][0], aF[buf][f][1], aF[buf][f][2], aF[buf][f][3],
                      aT + swz(off));
            }
        };
        auto ldB = [&](int buf, int ks) {
            #pragma unroll
            for (int g2 = 0; g2 < 2; g2++) {
                uint32_t off = (uint32_t)((wn * 32 + g2 * 16 + bn) * 128 + ks * 32 + bkO);
                ldsm4(bF[buf][g2][0], bF[buf][g2][1], bF[buf][g2][2], bF[buf][g2][3],
                      bT + swz(off));
            }
        };

        // software-pipelined ks loop: prefetch ks+1 fragments before MMAs of ks
        ldA(0, 0); ldB(0, 0);
        #pragma unroll
        for (int ks = 0; ks < 4; ks++) {
            const int cur = ks & 1, nxt = cur ^ 1;
            if (ks < 3) { ldA(nxt, ks + 1); ldB(nxt, ks + 1); }
            #pragma unroll
            for (int f = 0; f < 2; f++)
                #pragma unroll
                for (int g = 0; g < 4; g++)
                    mma16816(acc[f][g][0], acc[f][g][1], acc[f][g][2], acc[f][g][3],
                             aF[cur][f][0], aF[cur][f][1], aF[cur][f][2], aF[cur][f][3],
                             bF[cur][g >> 1][(g & 1) * 2], bF[cur][g >> 1][(g & 1) * 2 + 1]);
        }

        if (kt == 7) {
            #pragma unroll
            for (int f = 0; f < 2; f++) {
                #pragma unroll
                for (int g = 0; g < 4; g++) {
                    int nfirst = nt * 128 + wn * 32 + g * 8 + (lane & 3) * 2;
                    float e2a = g_e2[nfirst], e2b = g_e2[nfirst + 1];
                    uint32_t k0 = pack_key(e2a - 2.0f * acc[f][g][0], nfirst);
                    uint32_t k1 = pack_key(e2b - 2.0f * acc[f][g][1], nfirst + 1);
                    uint32_t k2 = pack_key(e2a - 2.0f * acc[f][g][2], nfirst);
                    uint32_t k3 = pack_key(e2b - 2.0f * acc[f][g][3], nfirst + 1);
                    INS_PK(2 * f,     k0);
                    INS_PK(2 * f,     k1);
                    INS_PK(2 * f + 1, k2);
                    INS_PK(2 * f + 1, k3);
                }
            }
        }
    }
    __syncthreads();   // all warps done reading sA/sB before candk aliases them

    // ---- merge: 16 thread-slots x top-4 = 64 packed candidates per pixel row ----
    const int tslot = wn * 4 + (lane & 3);      // 0..15
    #pragma unroll
    for (int f = 0; f < 2; f++) {
        #pragma unroll
        for (int h = 0; h < 2; h++) {
            int row = wm * 32 + f * 16 + h * 8 + (lane >> 2);
            #pragma unroll
            for (int k = 0; k < 4; k++)
                candk[row * 65 + tslot * 4 + k] = tk[2 * f + h][k];
        }
    }
    __syncthreads();

    if (t < 64) {
        const int row = t;
        const int n = n0 + row;
        uint32_t k1 = 0xFFFFFFFFu, k2 = 0xFFFFFFFFu;
        #pragma unroll 4
        for (int j = 0; j < 64; j++) {
            uint32_t k = candk[row * 65 + j];
            uint32_t hi = max(k, k1);
            k1 = min(k, k1);
            k2 = min(hi, k2);
        }
        const float d1 = key_d(k1), d2 = key_d(k2);
        // per-slot overflow mask: slot q may have dropped in-window candidates
        // only if its 4th-best is itself in-window
        uint32_t mask = 0;
        #pragma unroll
        for (int q = 0; q < 16; q++)
            if (key_d(candk[row * 65 + q * 4 + 3]) < d1 + W_AMB) mask |= (1u << q);
        g_idx[n] = (int)(k1 & 0x7FFu);
        g_d1[n] = d1;
        #pragma unroll 4
        for (int j = 0; j < 64; j++) g_cand[n][j] = candk[row * 65 + j];
        if (mask) {
            int p = atomicAdd(&g_nfix, 1);
            g_fix[p] = (int)(((uint32_t)n << 16) | mask);
            int r = atomicAdd(&g_nresc, 1);   // rescore provides the candidate-set min
            g_resc[r] = n;
        } else if (d2 - d1 < W_AMB) {
            int p = atomicAdd(&g_nresc, 1);
            g_resc[p] = n;
        }
    }
}

// ------------------------------------------------------------------
// rescore: exact fp32 over ONLY the in-window candidates, SEQUENTIAL
// k-order FMA (bitwise-identical arithmetic to the R1 baseline).
// Writes exact d to g_d1. Also covers flagged pixels (fixup merges after).
// ------------------------------------------------------------------
__global__ __launch_bounds__(256) void rescore_kernel(const float* __restrict__ cb) {
    __shared__ float zr[8][512];
    const int lane = threadIdx.x & 31;
    const int w = threadIdx.x >> 5;
    const int total = g_nresc;
    for (int p = blockIdx.x * 8 + w; p < total; p += gridDim.x * 8) {
        const int n = g_resc[p];
        const float thr = g_d1[n] + W_AMB;
        for (int i = lane; i < 128; i += 32)
            *(float4*)&zr[w][i * 4] = *(const float4*)&g_zt[(size_t)n * 512 + i * 4];
        __syncwarp();
        float best = FLT_MAX; int bid = 0x7fffffff;
        #pragma unroll
        for (int j0 = 0; j0 < 2; j0++) {
            int j = j0 * 32 + lane;
            float d = FLT_MAX; int id = 0x7fffffff;
            uint32_t key = g_cand[n][j];
            if (key_d(key) < thr) {
                id = (int)(key & 0x7FFu);
                const float4* cr4 = (const float4*)(cb + (size_t)id * 512);
                float dot = 0.f;
                #pragma unroll 4
                for (int c4 = 0; c4 < 128; c4++) {
                    float4 v = cr4[c4];
                    dot = fmaf(zr[w][c4 * 4 + 0], v.x, dot);
                    dot = fmaf(zr[w][c4 * 4 + 1], v.y, dot);
                    dot = fmaf(zr[w][c4 * 4 + 2], v.z, dot);
                    dot = fmaf(zr[w][c4 * 4 + 3], v.w, dot);
                }
                d = g_e2[id] - 2.0f * dot;
            }
            if (d < best || (d == best && id < bid)) { best = d; bid = id; }
        }
        #pragma unroll
        for (int o = 16; o; o >>= 1) {
            float od = __shfl_xor_sync(0xffffffffu, best, o);
            int   oi = __shfl_xor_sync(0xffffffffu, bid, o);
            if (od < best || (od == best && oi < bid)) { best = od; bid = oi; }
        }
        if (lane == 0) { g_idx[n] = bid; g_d1[n] = best; }
        __syncwarp();
    }
}

// ------------------------------------------------------------------
// fixup: warp per flagged pixel. Seeds from rescore's exact (d, idx),
// merges exact scans of flagged slots (coalesced slot-major g_cbS).
// Per-code dot = SEQUENTIAL c-order fmaf (R1 numerics). Runs AFTER rescore.
// ------------------------------------------------------------------
__global__ __launch_bounds__(256) void fixup_kernel() {
    __shared__ float zr[8][512];
    const int lane = threadIdx.x & 31;
    const int w = threadIdx.x >> 5;
    const int total = g_nfix;
    for (int p = blockIdx.x * 8 + w; p < total; p += gridDim.x * 8) {
        const uint32_t rec = (uint32_t)g_fix[p];
        const int n = (int)(rec >> 16);
        uint32_t mask = rec & 0xFFFFu;
        for (int i = lane; i < 128; i += 32)
            *(float4*)&zr[w][i * 4] = *(const float4*)&g_zt[(size_t)n * 512 + i * 4];
        __syncwarp();

        float best = g_d1[n];    // exact candidate-set min from rescore
        int   bid  = g_idx[n];

        // flagged slots: 4 codes/lane, coalesced slot-major loads
        while (mask) {
            int q = __ffs(mask) - 1; mask &= (mask - 1);
            const float* basep = g_cbS + ((size_t)q * 512) * 128 + lane * 4;
            float dot0 = 0.f, dot1 = 0.f, dot2 = 0.f, dot3 = 0.f;
            #pragma unroll 8
            for (int c = 0; c < 512; c++) {
                float zv = zr[w][c];
                float4 v = *(const float4*)(basep + (size_t)c * 128);
                dot0 = fmaf(zv, v.x, dot0);
                dot1 = fmaf(zv, v.y, dot1);
                dot2 = fmaf(zv, v.z, dot2);
                dot3 = fmaf(zv, v.w, dot3);
            }
            float dots[4] = { dot0, dot1, dot2, dot3 };
            #pragma unroll
            for (int j = 0; j < 4; j++) {
                int e = slot_code(q, lane * 4 + j);
                float d = g_e2[e] - 2.0f * dots[j];
                if (d < best || (d == best && e < bid)) { best = d; bid = e; }
            }
        }

        #pragma unroll
        for (int o = 16; o; o >>= 1) {
            float od = __shfl_xor_sync(0xffffffffu, best, o);
            int   oi = __shfl_xor_sync(0xffffffffu, bid, o);
            if (od < best || (od == best && oi < bid)) { best = od; bid = oi; }
        }
        if (lane == 0) { g_idx[n] = bid; g_d1[n] = best; }
        __syncwarp();
    }
}

// ------------------------------------------------------------------
// gather: chunked smem staging (64 channels/chunk) + coalesced
// transposed WRITE ONLY (loss comes from d values, no z read).
// ------------------------------------------------------------------
__global__ __launch_bounds__(256) void gather_kernel(
    const float* __restrict__ cb, float* __restrict__ out) {

    __shared__ float  smf[64 * 65];
    __shared__ int    idxs[64];

    const int t  = threadIdx.x;
    const int n0 = blockIdx.x * 64;
    if (t < 64) idxs[t] = g_idx[n0 + t];
    __syncthreads();

    const int b  = n0 >> 12;
    const int hw = n0 & 4095;
    const size_t base = (size_t)b * 512 * 4096 + hw;

    const int m  = t & 63;
    const int c0 = t >> 6;          // 0..3
    const int sr = t >> 4;          // staging row group 0..15
    const int sc = (t & 15) * 4;    // staging channel 0..60

    #pragma unroll 1
    for (int cc = 0; cc < 8; cc++) {
        #pragma unroll
        for (int it = 0; it < 4; it++) {
            int r = it * 16 + sr;
            float4 v = *(const float4*)(cb + (size_t)idxs[r] * 512 + cc * 64 + sc);
            smf[(sc + 0) * 65 + r] = v.x;
            smf[(sc + 1) * 65 + r] = v.y;
            smf[(sc + 2) * 65 + r] = v.z;
            smf[(sc + 3) * 65 + r] = v.w;
        }
        __syncthreads();
        #pragma unroll 4
        for (int i = 0; i < 16; i++) {
            int cl = c0 + i * 4;
            out[base + (size_t)(cc * 64 + cl) * 4096 + m] = smf[cl * 65 + m];
        }
        __syncthreads();
    }
}

// ------------------------------------------------------------------
// loss partials: blocks 0..63 sum g_z2p (16384 each), 64..67 sum g_d1.
// Fixed per-thread partitions + fp64 -> deterministic.
// ------------------------------------------------------------------
__global__ __launch_bounds__(256) void loss_part_kernel() {
    __shared__ double sd[256];
    const int t = threadIdx.x, b = blockIdx.x;
    const float* src = (b < 64) ? (g_z2p + (size_t)b * 16384)
                                : (g_d1 + (size_t)(b - 64) * 16384);
    double a0 = 0, a1 = 0, a2 = 0, a3 = 0;
    for (int i = t * 4; i < 16384; i += 1024) {
        float4 v = *(const float4*)(src + i);
        a0 += v.x; a1 += v.y; a2 += v.z; a3 += v.w;
    }
    sd[t] = (a0 + a1) + (a2 + a3);
    __syncthreads();
    #pragma unroll
    for (int s = 128; s; s >>= 1) {
        if (t < s) sd[t] += sd[t + s];
        __syncthreads();
    }
    if (t == 0) g_partial[b] = sd[0];
}

// ------------------------------------------------------------------
// finalize: loss = 1.25 * (sum_d + sum_z2) / zq_elems
// ------------------------------------------------------------------
__global__ void finalize_kernel(float* __restrict__ out, int out_size, int zq_elems) {
    if (threadIdx.x == 0) {
        double s = 0.0;
        for (int i = 0; i < 68; i++) s += g_partial[i];
        if (out_size > zq_elems)
            out[zq_elems] = (float)(1.25 * s / (double)zq_elems);
    }
}

// ------------------------------------------------------------------
// launch
// ------------------------------------------------------------------
extern "C" void kernel_launch(void* const* d_in, const int* in_sizes, int n_in,
                              void* d_out, int out_size) {
    const float* z  = (const float*)d_in[0];   // [16,512,64,64]
    const float* cb = (const float*)d_in[1];   // [2048,512]
    float* out = (float*)d_out;
    const int zq_elems = in_sizes[0];          // 33554432

    const int SMEM_MAIN = 65536 + 2 * 16384;   // A resident (64KB) + 2 B stages (32KB)
    cudaFuncSetAttribute(vq_mma_kernel,
                         cudaFuncAttributeMaxDynamicSharedMemorySize, SMEM_MAIN);

    prep_cb_kernel<<<1280, 256>>>(cb);                  // launch 0 (e2/bf16 + cbS build)
    prep_z_kernel<<<dim3(2048, 16), dim3(32, 8)>>>(z);  // launch 1
    vq_mma_kernel<<<1024, 256, SMEM_MAIN>>>();          // launch 2
    rescore_kernel<<<512, 256>>>(cb);                   // launch 3 -> profiled
    fixup_kernel<<<512, 256>>>();                       // launch 4 (after rescore)
    gather_kernel<<<1024, 256>>>(cb, out);              // launch 5
    loss_part_kernel<<<68, 256>>>();                    // launch 6
    finalize_kernel<<<1, 32>>>(out, out_size, zq_elems);// launch 7
}